// round 3
// baseline (speedup 1.0000x reference)
#include <cuda_runtime.h>

#define SEQ   512
#define BATCH 64
#define FEAT  512
#define COMP  256
#define NHEAD 8

// Scratch (allocation-free rule: __device__ globals)
__device__ float g_d3[(size_t)SEQ * BATCH * COMP];      // [32768][256]
__device__ float g_tv[(size_t)BATCH * SEQ * COMP];      // [64][512][256]
__device__ float g_d4[BATCH * COMP];                    // [64][256]
__device__ float g_y2[NHEAD * BATCH * COMP];            // [8][64][256]
__device__ float g_atts[NHEAD * BATCH * SEQ];           // [8][64][512]
__device__ float g_scores[NHEAD * BATCH * SEQ];
__device__ float g_vsp[8 * BATCH * NHEAD * COMP];       // [8 sb][64][2048]

// ---------------------------------------------------------------------------
// d4 = relu(d1 @ w1 + b1)   [64,256]
// ---------------------------------------------------------------------------
__global__ void k_d4(const float* __restrict__ d1, const float* __restrict__ w1,
                     const float* __restrict__ b1) {
    __shared__ float row[FEAT];
    int b = blockIdx.x, c = threadIdx.x;
    for (int i = c; i < FEAT; i += blockDim.x) row[i] = d1[b * FEAT + i];
    __syncthreads();
    float acc = b1[c];
#pragma unroll 8
    for (int d = 0; d < FEAT; d++) acc = fmaf(row[d], w1[d * COMP + c], acc);
    g_d4[b * COMP + c] = fmaxf(acc, 0.f);
}

// ---------------------------------------------------------------------------
// Old 64-row tile GEMM (used only by tiny k_y2). 256 threads, 8x8 microtile.
// ---------------------------------------------------------------------------
template <int K, int LDA>
__device__ __forceinline__ void gemm_tile64(const float* __restrict__ A,
                                            const float* __restrict__ Bm,
                                            float acc[8][8]) {
    __shared__ float As[16 * 64];
    __shared__ float Bs[16 * 256];
    int tid  = threadIdx.x;
    int am   = tid >> 2;
    int ak   = (tid & 3) << 2;
    int bn   = (tid & 63) << 2;
    int bk   = (tid >> 6) << 2;
    int rowb = (tid >> 5) << 3;
    int cb   = (tid & 31) << 2;

#pragma unroll
    for (int i = 0; i < 8; i++)
#pragma unroll
        for (int j = 0; j < 8; j++) acc[i][j] = 0.f;

    for (int k0 = 0; k0 < K; k0 += 16) {
        float4 av = *(const float4*)(A + am * LDA + k0 + ak);
        As[(ak + 0) * 64 + am] = av.x;
        As[(ak + 1) * 64 + am] = av.y;
        As[(ak + 2) * 64 + am] = av.z;
        As[(ak + 3) * 64 + am] = av.w;
#pragma unroll
        for (int i = 0; i < 4; i++) {
            *(float4*)(Bs + (bk + i) * 256 + bn) =
                *(const float4*)(Bm + (size_t)(k0 + bk + i) * 256 + bn);
        }
        __syncthreads();
#pragma unroll
        for (int kk = 0; kk < 16; kk++) {
            float4 a0 = *(const float4*)(As + kk * 64 + rowb);
            float4 a1 = *(const float4*)(As + kk * 64 + rowb + 4);
            float4 b0 = *(const float4*)(Bs + kk * 256 + cb);
            float4 b1 = *(const float4*)(Bs + kk * 256 + cb + 128);
            float a[8]  = {a0.x, a0.y, a0.z, a0.w, a1.x, a1.y, a1.z, a1.w};
            float bb[8] = {b0.x, b0.y, b0.z, b0.w, b1.x, b1.y, b1.z, b1.w};
#pragma unroll
            for (int i = 0; i < 8; i++)
#pragma unroll
                for (int j = 0; j < 8; j++)
                    acc[i][j] = fmaf(a[i], bb[j], acc[i][j]);
        }
        __syncthreads();
    }
}

// ---------------------------------------------------------------------------
// y2[h][b][c] = d4[b,:] @ W_h[256:512,:]   grid NHEAD, block 256.
// ---------------------------------------------------------------------------
__global__ void __launch_bounds__(256)
k_y2(const float* __restrict__ W) {
    int h = blockIdx.x;
    float acc[8][8];
    gemm_tile64<COMP, COMP>(g_d4, W + (size_t)h * 512 * 256 + 256 * 256, acc);
    int tid  = threadIdx.x;
    int rowb = (tid >> 5) << 3;
    int cb   = (tid & 31) << 2;
#pragma unroll
    for (int i = 0; i < 8; i++)
#pragma unroll
        for (int j = 0; j < 8; j++) {
            int c = (j < 4) ? cb + j : cb + 124 + j;
            g_y2[((size_t)h * 64 + rowb + i) * 256 + c] = acc[i][j];
        }
}

// ---------------------------------------------------------------------------
// 128x256 tile GEMM, double-buffered (Kc=8), 512 threads, 8x8 microtile.
// A: 128 rows row-major ld=LDA. Bm: [K][256] row-major.
// Thread t: rows (t>>5)*8..+7, cols (t&31)*4 {+0..3, +128..131}.
// ---------------------------------------------------------------------------
template <int K, int LDA>
__device__ __forceinline__ void gemm128(const float* __restrict__ A,
                                        const float* __restrict__ Bm,
                                        float acc[8][8]) {
    __shared__ float As[2][8 * 128];
    __shared__ float Bs[2][8 * 256];
    const int tid  = threadIdx.x;
    const int am   = tid >> 2;            // 0..127 (A row)
    const int ak   = (tid & 3) << 1;      // 0,2,4,6 (k chunk of 2)
    const int bn   = (tid & 63) << 2;     // 0..252
    const int bk   = tid >> 6;            // 0..7
    const int rowb = (tid >> 5) << 3;     // 0..120
    const int cb   = (tid & 31) << 2;     // 0..124

#pragma unroll
    for (int i = 0; i < 8; i++)
#pragma unroll
        for (int j = 0; j < 8; j++) acc[i][j] = 0.f;

    const float* aptr = A + (size_t)am * LDA + ak;
    const float* bptr = Bm + (size_t)bk * 256 + bn;

    // preload stage 0
    float2 pa  = *(const float2*)(aptr);
    float4 pb  = *(const float4*)(bptr);
    As[0][(ak + 0) * 128 + am] = pa.x;
    As[0][(ak + 1) * 128 + am] = pa.y;
    *(float4*)&Bs[0][bk * 256 + bn] = pb;
    __syncthreads();

    const int NS = K / 8;
#pragma unroll 2
    for (int st = 0; st < NS; st++) {
        const int cur = st & 1;
        if (st + 1 < NS) {
            pa = *(const float2*)(aptr + (st + 1) * 8);
            pb = *(const float4*)(bptr + (size_t)(st + 1) * 8 * 256);
        }
#pragma unroll
        for (int kk = 0; kk < 8; kk++) {
            float4 a0 = *(const float4*)(&As[cur][kk * 128 + rowb]);
            float4 a1 = *(const float4*)(&As[cur][kk * 128 + rowb + 4]);
            float4 b0 = *(const float4*)(&Bs[cur][kk * 256 + cb]);
            float4 b1 = *(const float4*)(&Bs[cur][kk * 256 + cb + 128]);
            float a[8]  = {a0.x, a0.y, a0.z, a0.w, a1.x, a1.y, a1.z, a1.w};
            float bb[8] = {b0.x, b0.y, b0.z, b0.w, b1.x, b1.y, b1.z, b1.w};
#pragma unroll
            for (int i = 0; i < 8; i++)
#pragma unroll
                for (int j = 0; j < 8; j++)
                    acc[i][j] = fmaf(a[i], bb[j], acc[i][j]);
        }
        if (st + 1 < NS) {
            const int nxt = cur ^ 1;
            As[nxt][(ak + 0) * 128 + am] = pa.x;
            As[nxt][(ak + 1) * 128 + am] = pa.y;
            *(float4*)&Bs[nxt][bk * 256 + bn] = pb;
        }
        __syncthreads();
    }
}

// ---------------------------------------------------------------------------
// Fused projection over 2 s-values per block (M=128 rows).
// path 0 -> d3 = relu(d2@w1 + b1); path 1 -> tv[b][s][:] = tanh(d2@wv)
// grid (SEQ/2, 2), block 512.
// ---------------------------------------------------------------------------
__global__ void __launch_bounds__(512)
k_proj(const float* __restrict__ d2, const float* __restrict__ w1,
       const float* __restrict__ b1, const float* __restrict__ wv) {
    const int s0 = blockIdx.x * 2;
    const int path = blockIdx.y;
    const float* A = d2 + (size_t)s0 * 64 * FEAT;
    float acc[8][8];
    gemm128<FEAT, FEAT>(A, path == 0 ? w1 : wv, acc);

    const int tid  = threadIdx.x;
    const int rowb = (tid >> 5) << 3;
    const int cb   = (tid & 31) << 2;
    if (path == 0) {
#pragma unroll
        for (int i = 0; i < 8; i++) {
            size_t r = (size_t)s0 * 64 + rowb + i;
#pragma unroll
            for (int j = 0; j < 8; j++) {
                int c = (j < 4) ? cb + j : cb + 124 + j;
                g_d3[r * 256 + c] = fmaxf(acc[i][j] + __ldg(b1 + c), 0.f);
            }
        }
    } else {
#pragma unroll
        for (int i = 0; i < 8; i++) {
            int r = rowb + i;
            int s = s0 + (r >> 6);
            int b = r & 63;
#pragma unroll
            for (int j = 0; j < 8; j++) {
                int c = (j < 4) ? cb + j : cb + 124 + j;
                g_tv[((size_t)b * 512 + s) * 256 + c] = tanhf(acc[i][j]);
            }
        }
    }
}

// ---------------------------------------------------------------------------
// atts[h][b][s] = sum_c tanh( d3[s]@W_h[:256] + y2[h] )[b,c] * P[h][c]
// grid (SEQ/2, NHEAD), block 512. M=128 (2 s-values), K=256.
// ---------------------------------------------------------------------------
__global__ void __launch_bounds__(512)
k_att(const float* __restrict__ W, const float* __restrict__ P) {
    __shared__ float Ps[256];
    const int h = blockIdx.y;
    const int tid = threadIdx.x;
    if (tid < 256) Ps[tid] = P[h * 256 + tid];  // visible after gemm's syncs

    const float* A = g_d3 + (size_t)blockIdx.x * 128 * 256;
    float acc[8][8];
    gemm128<COMP, COMP>(A, W + (size_t)h * 512 * 256, acc);

    const int rowb = (tid >> 5) << 3;
    const int cb   = (tid & 31) << 2;
    const int lane = tid & 31;
    const int s0   = blockIdx.x * 2;
    const float* y2h = g_y2 + (size_t)h * 64 * 256;
#pragma unroll
    for (int i = 0; i < 8; i++) {
        int r = rowb + i;
        int s = s0 + (r >> 6);
        int b = r & 63;
        float ps = 0.f;
#pragma unroll
        for (int j = 0; j < 8; j++) {
            int c = (j < 4) ? cb + j : cb + 124 + j;
            ps += tanhf(acc[i][j] + y2h[b * 256 + c]) * Ps[c];
        }
#pragma unroll
        for (int off = 16; off > 0; off >>= 1)
            ps += __shfl_xor_sync(0xffffffffu, ps, off);
        if (lane == 0)
            g_atts[((size_t)h * 64 + b) * 512 + s] = ps;
    }
}

// ---------------------------------------------------------------------------
// Row softmax over S=512. grid NHEAD*BATCH, block 256.
// ---------------------------------------------------------------------------
__global__ void k_softmax() {
    __shared__ float red[256];
    int row = blockIdx.x, tid = threadIdx.x;
    const float* a = g_atts + (size_t)row * 512;
    float v0 = a[tid], v1 = a[tid + 256];
    red[tid] = fmaxf(v0, v1);
    __syncthreads();
    for (int o = 128; o > 0; o >>= 1) {
        if (tid < o) red[tid] = fmaxf(red[tid], red[tid + o]);
        __syncthreads();
    }
    float m = red[0];
    __syncthreads();
    float e0 = expf(v0 - m), e1 = expf(v1 - m);
    red[tid] = e0 + e1;
    __syncthreads();
    for (int o = 128; o > 0; o >>= 1) {
        if (tid < o) red[tid] += red[tid + o];
        __syncthreads();
    }
    float inv = 1.f / red[0];
    g_scores[(size_t)row * 512 + tid]       = e0 * inv;
    g_scores[(size_t)row * 512 + tid + 256] = e1 * inv;
}

// ---------------------------------------------------------------------------
// Partial vs over s-chunks: vsp[sb][b][h*256+c] = sum_{s in chunk} scores*tv
// grid (BATCH, 8), block 256.
// ---------------------------------------------------------------------------
__global__ void __launch_bounds__(256)
k_out1() {
    __shared__ float sc[512];   // [h][64]
    int b = blockIdx.x, sb = blockIdx.y, tid = threadIdx.x;
    for (int i = tid; i < 512; i += 256) {
        int h = i >> 6, ss = i & 63;
        sc[i] = g_scores[((size_t)h * 64 + b) * 512 + sb * 64 + ss];
    }
    __syncthreads();
    float acc[NHEAD] = {0.f, 0.f, 0.f, 0.f, 0.f, 0.f, 0.f, 0.f};
    const float* tvb = g_tv + ((size_t)b * 512 + sb * 64) * 256 + tid;
    for (int ss = 0; ss < 64; ss++) {
        float t = tvb[(size_t)ss * 256];
#pragma unroll
        for (int h = 0; h < NHEAD; h++) acc[h] = fmaf(sc[h * 64 + ss], t, acc[h]);
    }
#pragma unroll
    for (int h = 0; h < NHEAD; h++)
        g_vsp[((size_t)sb * 64 + b) * 2048 + h * 256 + tid] = acc[h];
}

// ---------------------------------------------------------------------------
// Reduce partials + final cc: out = relu(vs_flat @ wcc + bcc). grid 64, blk 128
// ---------------------------------------------------------------------------
__global__ void __launch_bounds__(128)
k_out2(const float* __restrict__ wcc, const float* __restrict__ bcc,
       float* __restrict__ out) {
    __shared__ float vsf[2048];
    int b = blockIdx.x, tid = threadIdx.x;
    for (int i = tid; i < 2048; i += 128) {
        float v = 0.f;
#pragma unroll
        for (int sb = 0; sb < 8; sb++)
            v += g_vsp[((size_t)sb * 64 + b) * 2048 + i];
        vsf[i] = v;
    }
    __syncthreads();
    float o = bcc[tid];
#pragma unroll 8
    for (int i = 0; i < 2048; i++) o = fmaf(vsf[i], wcc[i * 128 + tid], o);
    out[b * 128 + tid] = fmaxf(o, 0.f);
}

// ---------------------------------------------------------------------------
extern "C" void kernel_launch(void* const* d_in, const int* in_sizes, int n_in,
                              void* d_out, int out_size) {
    const float* d1  = (const float*)d_in[0];
    const float* d2  = (const float*)d_in[1];
    const float* w1  = (const float*)d_in[2];
    const float* b1  = (const float*)d_in[3];
    const float* W   = (const float*)d_in[4];
    const float* P   = (const float*)d_in[5];
    const float* wv  = (const float*)d_in[6];
    const float* wcc = (const float*)d_in[7];
    const float* bcc = (const float*)d_in[8];
    float* out = (float*)d_out;

    k_d4<<<BATCH, COMP>>>(d1, w1, b1);
    k_y2<<<NHEAD, 256>>>(W);
    k_proj<<<dim3(SEQ / 2, 2), 512>>>(d2, w1, b1, wv);
    k_att<<<dim3(SEQ / 2, NHEAD), 512>>>(W, P);
    k_softmax<<<NHEAD * BATCH, 256>>>();
    k_out1<<<dim3(BATCH, 8), 256>>>();
    k_out2<<<BATCH, 128>>>(wcc, bcc, out);
}

// round 6
// speedup vs baseline: 1.2784x; 1.2784x over previous
#include <cuda_runtime.h>
#include <cuda_bf16.h>
#include <cstdint>

#define SEQ   512
#define BATCH 64
#define FEAT  512
#define COMP  256
#define NHEAD 8

// Scratch (allocation-free rule: __device__ globals)
__device__ uint32_t g_d3p[(size_t)SEQ * BATCH * 256];   // packed bf16 hi/lo pairs per row:
                                                        // words 0..127 = hi pairs (k,k+1), 128..255 = lo
__device__ float g_tv[(size_t)BATCH * SEQ * COMP];      // [64][512][256]
__device__ float g_d4[BATCH * COMP];                    // [64][256]
__device__ float g_y2[NHEAD * BATCH * COMP];            // [8][64][256]
__device__ float g_attsp[2 * NHEAD * BATCH * SEQ];      // two c-half partials
__device__ float g_scores[NHEAD * BATCH * SEQ];
__device__ float g_vsp[8 * BATCH * NHEAD * COMP];       // [8 sb][64][2048]
// W^T bf16 split: [h][c][k] (first 256 k-rows of W_h)
__device__ __align__(16) __nv_bfloat16 g_Wth[NHEAD * 256 * 256];
__device__ __align__(16) __nv_bfloat16 g_Wtl[NHEAD * 256 * 256];

// bf16 split of a pair of floats -> packed hi and lo words
__device__ __forceinline__ void split2(float a, float b, uint32_t& hi, uint32_t& lo) {
    __nv_bfloat16 ha = __float2bfloat16_rn(a);
    __nv_bfloat16 hb = __float2bfloat16_rn(b);
    __nv_bfloat16 la = __float2bfloat16_rn(a - __bfloat162float(ha));
    __nv_bfloat16 lb = __float2bfloat16_rn(b - __bfloat162float(hb));
    hi = (uint32_t)__bfloat16_as_ushort(ha) | ((uint32_t)__bfloat16_as_ushort(hb) << 16);
    lo = (uint32_t)__bfloat16_as_ushort(la) | ((uint32_t)__bfloat16_as_ushort(lb) << 16);
}

__device__ __forceinline__ void mma16816(float c[4], uint32_t a0, uint32_t a1,
                                         uint32_t a2, uint32_t a3,
                                         uint32_t b0, uint32_t b1) {
    asm volatile(
        "mma.sync.aligned.m16n8k16.row.col.f32.bf16.bf16.f32 "
        "{%0,%1,%2,%3}, {%4,%5,%6,%7}, {%8,%9}, {%0,%1,%2,%3};"
        : "+f"(c[0]), "+f"(c[1]), "+f"(c[2]), "+f"(c[3])
        : "r"(a0), "r"(a1), "r"(a2), "r"(a3), "r"(b0), "r"(b1));
}

// ===========================================================================
// d4 = relu(d1 @ w1 + b1)   [64,256]
// ===========================================================================
__global__ void k_d4(const float* __restrict__ d1, const float* __restrict__ w1,
                     const float* __restrict__ b1) {
    __shared__ float row[FEAT];
    int b = blockIdx.x, c = threadIdx.x;
    for (int i = c; i < FEAT; i += blockDim.x) row[i] = d1[b * FEAT + i];
    __syncthreads();
    float acc = b1[c];
#pragma unroll 8
    for (int d = 0; d < FEAT; d++) acc = fmaf(row[d], w1[d * COMP + c], acc);
    g_d4[b * COMP + c] = fmaxf(acc, 0.f);
}

// ===========================================================================
// 64-row fp32 tile GEMM (round-2 proven). 256 threads, 8x8 microtile.
// ===========================================================================
template <int K, int LDA>
__device__ __forceinline__ void gemm_tile64(const float* __restrict__ A,
                                            const float* __restrict__ Bm,
                                            float acc[8][8]) {
    __shared__ float As[16 * 64];
    __shared__ float Bs[16 * 256];
    int tid  = threadIdx.x;
    int am   = tid >> 2;
    int ak   = (tid & 3) << 2;
    int bn   = (tid & 63) << 2;
    int bk   = (tid >> 6) << 2;
    int rowb = (tid >> 5) << 3;
    int cb   = (tid & 31) << 2;

#pragma unroll
    for (int i = 0; i < 8; i++)
#pragma unroll
        for (int j = 0; j < 8; j++) acc[i][j] = 0.f;

    for (int k0 = 0; k0 < K; k0 += 16) {
        float4 av = *(const float4*)(A + am * LDA + k0 + ak);
        As[(ak + 0) * 64 + am] = av.x;
        As[(ak + 1) * 64 + am] = av.y;
        As[(ak + 2) * 64 + am] = av.z;
        As[(ak + 3) * 64 + am] = av.w;
#pragma unroll
        for (int i = 0; i < 4; i++) {
            *(float4*)(Bs + (bk + i) * 256 + bn) =
                *(const float4*)(Bm + (size_t)(k0 + bk + i) * 256 + bn);
        }
        __syncthreads();
#pragma unroll
        for (int kk = 0; kk < 16; kk++) {
            float4 a0 = *(const float4*)(As + kk * 64 + rowb);
            float4 a1 = *(const float4*)(As + kk * 64 + rowb + 4);
            float4 b0 = *(const float4*)(Bs + kk * 256 + cb);
            float4 b1 = *(const float4*)(Bs + kk * 256 + cb + 128);
            float a[8]  = {a0.x, a0.y, a0.z, a0.w, a1.x, a1.y, a1.z, a1.w};
            float bb[8] = {b0.x, b0.y, b0.z, b0.w, b1.x, b1.y, b1.z, b1.w};
#pragma unroll
            for (int i = 0; i < 8; i++)
#pragma unroll
                for (int j = 0; j < 8; j++)
                    acc[i][j] = fmaf(a[i], bb[j], acc[i][j]);
        }
        __syncthreads();
    }
}

// ===========================================================================
// y2[h][b][c] = d4[b,:] @ W_h[256:512,:]   grid NHEAD, block 256.
// ===========================================================================
__global__ void __launch_bounds__(256)
k_y2(const float* __restrict__ W) {
    int h = blockIdx.x;
    float acc[8][8];
    gemm_tile64<COMP, COMP>(g_d4, W + (size_t)h * 512 * 256 + 256 * 256, acc);
    int tid  = threadIdx.x;
    int rowb = (tid >> 5) << 3;
    int cb   = (tid & 31) << 2;
#pragma unroll
    for (int i = 0; i < 8; i++)
#pragma unroll
        for (int j = 0; j < 8; j++) {
            int c = (j < 4) ? cb + j : cb + 124 + j;
            g_y2[((size_t)h * 64 + rowb + i) * 256 + c] = acc[i][j];
        }
}

// ===========================================================================
// W^T split prep: g_Wth/l[h][c][k] = bf16 split of W[h][k][c], k<256.
// grid NHEAD, block 256.
// ===========================================================================
__global__ void __launch_bounds__(256)
k_wsplit(const float* __restrict__ W) {
    int h = blockIdx.x;
    for (int i = threadIdx.x; i < 256 * 256; i += 256) {
        int k = i >> 8, c = i & 255;
        float v = W[((size_t)h * 512 + k) * 256 + c];
        __nv_bfloat16 hi = __float2bfloat16_rn(v);
        __nv_bfloat16 lo = __float2bfloat16_rn(v - __bfloat162float(hi));
        size_t o = ((size_t)h * 256 + c) * 256 + k;
        g_Wth[o] = hi;
        g_Wtl[o] = lo;
    }
}

// ===========================================================================
// Fused projection (round-2 config): grid (SEQ, 2), block 256.
// path 0 -> g_d3p = packed bf16 hi/lo of relu(d2@w1 + b1)
// path 1 -> tv[b][s][:] = tanh(d2@wv)
// ===========================================================================
__global__ void __launch_bounds__(256)
k_proj(const float* __restrict__ d2, const float* __restrict__ w1,
       const float* __restrict__ b1, const float* __restrict__ wv) {
    int s = blockIdx.x;
    int path = blockIdx.y;
    const float* A = d2 + (size_t)s * 64 * FEAT;
    float acc[8][8];
    gemm_tile64<FEAT, FEAT>(A, path == 0 ? w1 : wv, acc);

    int tid  = threadIdx.x;
    int rowb = (tid >> 5) << 3;
    int cb   = (tid & 31) << 2;
    if (path == 0) {
        int p0 = cb >> 1;
#pragma unroll
        for (int i = 0; i < 8; i++) {
            size_t r = (size_t)s * 64 + rowb + i;
            uint32_t* dst = g_d3p + r * 256;
            float v[8];
#pragma unroll
            for (int j = 0; j < 8; j++) {
                int c = (j < 4) ? cb + j : cb + 124 + j;
                v[j] = fmaxf(acc[i][j] + __ldg(b1 + c), 0.f);
            }
            uint32_t hi, lo;
            split2(v[0], v[1], hi, lo); dst[p0] = hi;          dst[128 + p0] = lo;
            split2(v[2], v[3], hi, lo); dst[p0 + 1] = hi;      dst[128 + p0 + 1] = lo;
            split2(v[4], v[5], hi, lo); dst[64 + p0] = hi;     dst[192 + p0] = lo;
            split2(v[6], v[7], hi, lo); dst[64 + p0 + 1] = hi; dst[192 + p0 + 1] = lo;
        }
    } else {
#pragma unroll
        for (int i = 0; i < 8; i++) {
            int b = rowb + i;
#pragma unroll
            for (int j = 0; j < 8; j++) {
                int c = (j < 4) ? cb + j : cb + 124 + j;
                g_tv[((size_t)b * 512 + s) * 256 + c] = tanhf(acc[i][j]);
            }
        }
    }
}

// ===========================================================================
// k_att via mma.sync (HMMA bf16-split). grid (2 cx, 8 h, 256 sblk), block 256.
// CTA: D[128 rows][128 cols] over K=256 (4 chunks of 64).
// Warp w: rows 16w..16w+15. Smem word layout (uint32 units):
//   Ah [0,4608)  Al [4608,9216)  Bh [9216,13824)  Bl [13824,18432)
//   y2s [18432,26880) as [b][132]  Ps [26880,27008)
// Row pitch = 36 words (32 data + 4 pad) -> conflict-free frag LDS.
// ===========================================================================
#define ATT_SMEM_WORDS 27008
#define ATT_SMEM_BYTES (ATT_SMEM_WORDS * 4)

__global__ void __launch_bounds__(256, 2)
k_att_mma(const float* __restrict__ P) {
    extern __shared__ __align__(16) uint32_t sm[];
    uint32_t* Ah = sm;
    uint32_t* Al = sm + 4608;
    uint32_t* Bh = sm + 9216;
    uint32_t* Bl = sm + 13824;
    float*    y2s = (float*)(sm + 18432);   // [b 0..63][pitch 132]
    float*    Ps  = (float*)(sm + 26880);

    const int cx = blockIdx.x, h = blockIdx.y, zb = blockIdx.z;
    const int m0 = zb * 128;
    const int tid = threadIdx.x;
    const int wid = tid >> 5;
    const int lane = tid & 31;
    const int g  = lane >> 2;       // group id (0..7)
    const int tg = lane & 3;        // thread-in-group
    const int m0w = wid * 16;       // warp row base within tile

    // y2 slice + P (once)
    for (int i = tid; i < 8192; i += 256) {
        int b = i >> 7, cc = i & 127;
        y2s[b * 132 + cc] = g_y2[((size_t)h * 64 + b) * 256 + cx * 128 + cc];
    }
    if (tid < 128) Ps[tid] = P[h * 256 + cx * 128 + tid];

    float acc[16][4];
#pragma unroll
    for (int n8 = 0; n8 < 16; n8++)
#pragma unroll
        for (int e = 0; e < 4; e++) acc[n8][e] = 0.f;

    const __nv_bfloat16* Wh = g_Wth + ((size_t)h * 256 + cx * 128) * 256;
    const __nv_bfloat16* Wl = g_Wtl + ((size_t)h * 256 + cx * 128) * 256;

    for (int ch = 0; ch < 4; ch++) {
        const int kc0 = ch * 64;          // chunk k base (bf16 units)
        __syncthreads();                  // prev compute done (and y2/Ps on ch 0)

        // ---- copy A chunk: 2048 uint4 (hi+lo) ----
        for (int t = tid; t < 2048; t += 256) {
            int r = t >> 4, j = t & 15;
            int plane = j >> 3, kw = (j & 7) * 4;   // word offset in row chunk
            const uint4 v = *(const uint4*)(g_d3p + (size_t)(m0 + r) * 256 +
                                            plane * 128 + (kc0 >> 1) + kw);
            uint32_t* dstp = (plane ? Al : Ah) + r * 36 + kw;
            *(uint4*)dstp = v;
        }
        // ---- copy B chunk: 2048 uint4 (hi+lo) ----
        for (int t = tid; t < 2048; t += 256) {
            int n = t >> 4, j = t & 15;
            int plane = j >> 3, j8 = j & 7;
            const uint4* srow = (const uint4*)((plane ? Wl : Wh) + (size_t)n * 256 + kc0);
            uint32_t* dstp = (plane ? Bl : Bh) + n * 36 + j8 * 4;
            *(uint4*)dstp = srow[j8];
        }
        __syncthreads();

        // ---- compute: 4 k-steps of 16 ----
#pragma unroll
        for (int ks = 0; ks < 4; ks++) {
            const int kw0 = ks * 8;
            const int ra = (m0w + g) * 36 + kw0 + tg;
            const int rb = (m0w + g + 8) * 36 + kw0 + tg;
            uint32_t ah0 = Ah[ra],     ah1 = Ah[rb];
            uint32_t ah2 = Ah[ra + 4], ah3 = Ah[rb + 4];
            uint32_t al0 = Al[ra],     al1 = Al[rb];
            uint32_t al2 = Al[ra + 4], al3 = Al[rb + 4];
#pragma unroll
            for (int n8 = 0; n8 < 16; n8++) {
                const int nb = (n8 * 8 + g) * 36 + kw0 + tg;
                uint32_t b0 = Bh[nb], b1 = Bh[nb + 4];
                uint32_t c0 = Bl[nb], c1 = Bl[nb + 4];
                mma16816(acc[n8], ah0, ah1, ah2, ah3, b0, b1);
                mma16816(acc[n8], ah0, ah1, ah2, ah3, c0, c1);
                mma16816(acc[n8], al0, al1, al2, al3, b0, b1);
            }
        }
    }

    // ---- epilogue: ps[row] = sum_cc tanh(D + y2) * P, quad-reduce ----
    const int r0 = m0w + g, r1 = r0 + 8;           // local rows
    const int b0 = (m0 + r0) & 63, b1v = (m0 + r1) & 63;
    float ps0 = 0.f, ps1 = 0.f;
#pragma unroll
    for (int n8 = 0; n8 < 16; n8++) {
        const int cc0 = n8 * 8 + tg * 2;
        const float p0 = Ps[cc0], p1 = Ps[cc0 + 1];
        ps0 += tanhf(acc[n8][0] + y2s[b0 * 132 + cc0]) * p0
             + tanhf(acc[n8][1] + y2s[b0 * 132 + cc0 + 1]) * p1;
        ps1 += tanhf(acc[n8][2] + y2s[b1v * 132 + cc0]) * p0
             + tanhf(acc[n8][3] + y2s[b1v * 132 + cc0 + 1]) * p1;
    }
    ps0 += __shfl_xor_sync(0xffffffffu, ps0, 1);
    ps0 += __shfl_xor_sync(0xffffffffu, ps0, 2);
    ps1 += __shfl_xor_sync(0xffffffffu, ps1, 1);
    ps1 += __shfl_xor_sync(0xffffffffu, ps1, 2);
    if (tg == 0) {
        float* dst = g_attsp + (size_t)cx * (NHEAD * BATCH * SEQ);
        const int R0 = m0 + r0, R1 = m0 + r1;
        dst[((size_t)h * 64 + (R0 & 63)) * 512 + (R0 >> 6)] = ps0;
        dst[((size_t)h * 64 + (R1 & 63)) * 512 + (R1 >> 6)] = ps1;
    }
}

// ===========================================================================
// Row softmax over S=512, summing the two c-half partials. grid 512, blk 256.
// ===========================================================================
__global__ void k_softmax() {
    __shared__ float red[256];
    int row = blockIdx.x, tid = threadIdx.x;
    const float* a0 = g_attsp + (size_t)row * 512;
    const float* a1 = a0 + (size_t)NHEAD * BATCH * SEQ;
    float v0 = a0[tid] + a1[tid];
    float v1 = a0[tid + 256] + a1[tid + 256];
    red[tid] = fmaxf(v0, v1);
    __syncthreads();
    for (int o = 128; o > 0; o >>= 1) {
        if (tid < o) red[tid] = fmaxf(red[tid], red[tid + o]);
        __syncthreads();
    }
    float m = red[0];
    __syncthreads();
    float e0 = expf(v0 - m), e1 = expf(v1 - m);
    red[tid] = e0 + e1;
    __syncthreads();
    for (int o = 128; o > 0; o >>= 1) {
        if (tid < o) red[tid] += red[tid + o];
        __syncthreads();
    }
    float inv = 1.f / red[0];
    g_scores[(size_t)row * 512 + tid]       = e0 * inv;
    g_scores[(size_t)row * 512 + tid + 256] = e1 * inv;
}

// ===========================================================================
// Partial vs over s-chunks. grid (BATCH, 8), block 256.
// ===========================================================================
__global__ void __launch_bounds__(256)
k_out1() {
    __shared__ float sc[512];
    int b = blockIdx.x, sb = blockIdx.y, tid = threadIdx.x;
    for (int i = tid; i < 512; i += 256) {
        int h = i >> 6, ss = i & 63;
        sc[i] = g_scores[((size_t)h * 64 + b) * 512 + sb * 64 + ss];
    }
    __syncthreads();
    float acc[NHEAD] = {0.f, 0.f, 0.f, 0.f, 0.f, 0.f, 0.f, 0.f};
    const float* tvb = g_tv + ((size_t)b * 512 + sb * 64) * 256 + tid;
    for (int ss = 0; ss < 64; ss++) {
        float t = tvb[(size_t)ss * 256];
#pragma unroll
        for (int h = 0; h < NHEAD; h++) acc[h] = fmaf(sc[h * 64 + ss], t, acc[h]);
    }
#pragma unroll
    for (int h = 0; h < NHEAD; h++)
        g_vsp[((size_t)sb * 64 + b) * 2048 + h * 256 + tid] = acc[h];
}

// ===========================================================================
// Reduce partials + final cc. grid 64, block 128.
// ===========================================================================
__global__ void __launch_bounds__(128)
k_out2(const float* __restrict__ wcc, const float* __restrict__ bcc,
       float* __restrict__ out) {
    __shared__ float vsf[2048];
    int b = blockIdx.x, tid = threadIdx.x;
    for (int i = tid; i < 2048; i += 128) {
        float v = 0.f;
#pragma unroll
        for (int sb = 0; sb < 8; sb++)
            v += g_vsp[((size_t)sb * 64 + b) * 2048 + i];
        vsf[i] = v;
    }
    __syncthreads();
    float o = bcc[tid];
#pragma unroll 8
    for (int i = 0; i < 2048; i++) o = fmaf(vsf[i], wcc[i * 128 + tid], o);
    out[b * 128 + tid] = fmaxf(o, 0.f);
}

// ===========================================================================
extern "C" void kernel_launch(void* const* d_in, const int* in_sizes, int n_in,
                              void* d_out, int out_size) {
    const float* d1  = (const float*)d_in[0];
    const float* d2  = (const float*)d_in[1];
    const float* w1  = (const float*)d_in[2];
    const float* b1  = (const float*)d_in[3];
    const float* W   = (const float*)d_in[4];
    const float* P   = (const float*)d_in[5];
    const float* wv  = (const float*)d_in[6];
    const float* wcc = (const float*)d_in[7];
    const float* bcc = (const float*)d_in[8];
    float* out = (float*)d_out;

    cudaFuncSetAttribute(k_att_mma, cudaFuncAttributeMaxDynamicSharedMemorySize,
                         ATT_SMEM_BYTES);

    k_d4<<<BATCH, COMP>>>(d1, w1, b1);
    k_y2<<<NHEAD, 256>>>(W);
    k_wsplit<<<NHEAD, 256>>>(W);
    k_proj<<<dim3(SEQ, 2), 256>>>(d2, w1, b1, wv);
    k_att_mma<<<dim3(2, NHEAD, SEQ / 2), 256, ATT_SMEM_BYTES>>>(P);
    k_softmax<<<NHEAD * BATCH, 256>>>();
    k_out1<<<dim3(BATCH, 8), 256>>>();
    k_out2<<<BATCH, 128>>>(wcc, bcc, out);
}

// round 7
// speedup vs baseline: 1.4705x; 1.1502x over previous
#include <cuda_runtime.h>
#include <cuda_bf16.h>
#include <cstdint>

#define SEQ   512
#define BATCH 64
#define FEAT  512
#define COMP  256
#define NHEAD 8

// Scratch (allocation-free rule: __device__ globals)
__device__ uint32_t g_d2p[(size_t)SEQ * BATCH * 512];   // d2 bf16 split: [row][256 hi | 256 lo] words
__device__ uint32_t g_d3p[(size_t)SEQ * BATCH * 256];   // d3 bf16 split: [row][128 hi | 128 lo] words
__device__ float g_tv[(size_t)BATCH * SEQ * COMP];      // [64][512][256]
__device__ float g_d4[BATCH * COMP];                    // [64][256]
__device__ float g_y2[NHEAD * BATCH * COMP];            // [8][64][256]
__device__ float g_attsp[2 * NHEAD * BATCH * SEQ];      // two c-half partials
__device__ float g_scores[NHEAD * BATCH * SEQ];
__device__ float g_vsp[8 * BATCH * NHEAD * COMP];       // [8 sb][64][2048]
// W^T bf16 split for k_att: [h][c][k<256]
__device__ __align__(16) __nv_bfloat16 g_Wth[NHEAD * 256 * 256];
__device__ __align__(16) __nv_bfloat16 g_Wtl[NHEAD * 256 * 256];
// w1/wv transposed split for k_proj: [path][c][k<512]
__device__ __align__(16) __nv_bfloat16 g_wpth[2 * 256 * 512];
__device__ __align__(16) __nv_bfloat16 g_wptl[2 * 256 * 512];

// bf16 split of a pair of floats -> packed hi and lo words
__device__ __forceinline__ void split2(float a, float b, uint32_t& hi, uint32_t& lo) {
    __nv_bfloat16 ha = __float2bfloat16_rn(a);
    __nv_bfloat16 hb = __float2bfloat16_rn(b);
    __nv_bfloat16 la = __float2bfloat16_rn(a - __bfloat162float(ha));
    __nv_bfloat16 lb = __float2bfloat16_rn(b - __bfloat162float(hb));
    hi = (uint32_t)__bfloat16_as_ushort(ha) | ((uint32_t)__bfloat16_as_ushort(hb) << 16);
    lo = (uint32_t)__bfloat16_as_ushort(la) | ((uint32_t)__bfloat16_as_ushort(lb) << 16);
}

__device__ __forceinline__ void mma16816(float c[4], uint32_t a0, uint32_t a1,
                                         uint32_t a2, uint32_t a3,
                                         uint32_t b0, uint32_t b1) {
    asm volatile(
        "mma.sync.aligned.m16n8k16.row.col.f32.bf16.bf16.f32 "
        "{%0,%1,%2,%3}, {%4,%5,%6,%7}, {%8,%9}, {%0,%1,%2,%3};"
        : "+f"(c[0]), "+f"(c[1]), "+f"(c[2]), "+f"(c[3])
        : "r"(a0), "r"(a1), "r"(a2), "r"(a3), "r"(b0), "r"(b1));
}

// ===========================================================================
// d4 = relu(d1 @ w1 + b1)   [64,256]
// ===========================================================================
__global__ void k_d4(const float* __restrict__ d1, const float* __restrict__ w1,
                     const float* __restrict__ b1) {
    __shared__ float row[FEAT];
    int b = blockIdx.x, c = threadIdx.x;
    for (int i = c; i < FEAT; i += blockDim.x) row[i] = d1[b * FEAT + i];
    __syncthreads();
    float acc = b1[c];
#pragma unroll 8
    for (int d = 0; d < FEAT; d++) acc = fmaf(row[d], w1[d * COMP + c], acc);
    g_d4[b * COMP + c] = fmaxf(acc, 0.f);
}

// ===========================================================================
// 64-row fp32 tile GEMM (round-2 proven). 256 threads, 8x8 microtile.
// ===========================================================================
template <int K, int LDA>
__device__ __forceinline__ void gemm_tile64(const float* __restrict__ A,
                                            const float* __restrict__ Bm,
                                            float acc[8][8]) {
    __shared__ float As[16 * 64];
    __shared__ float Bs[16 * 256];
    int tid  = threadIdx.x;
    int am   = tid >> 2;
    int ak   = (tid & 3) << 2;
    int bn   = (tid & 63) << 2;
    int bk   = (tid >> 6) << 2;
    int rowb = (tid >> 5) << 3;
    int cb   = (tid & 31) << 2;

#pragma unroll
    for (int i = 0; i < 8; i++)
#pragma unroll
        for (int j = 0; j < 8; j++) acc[i][j] = 0.f;

    for (int k0 = 0; k0 < K; k0 += 16) {
        float4 av = *(const float4*)(A + am * LDA + k0 + ak);
        As[(ak + 0) * 64 + am] = av.x;
        As[(ak + 1) * 64 + am] = av.y;
        As[(ak + 2) * 64 + am] = av.z;
        As[(ak + 3) * 64 + am] = av.w;
#pragma unroll
        for (int i = 0; i < 4; i++) {
            *(float4*)(Bs + (bk + i) * 256 + bn) =
                *(const float4*)(Bm + (size_t)(k0 + bk + i) * 256 + bn);
        }
        __syncthreads();
#pragma unroll
        for (int kk = 0; kk < 16; kk++) {
            float4 a0 = *(const float4*)(As + kk * 64 + rowb);
            float4 a1 = *(const float4*)(As + kk * 64 + rowb + 4);
            float4 b0 = *(const float4*)(Bs + kk * 256 + cb);
            float4 b1 = *(const float4*)(Bs + kk * 256 + cb + 128);
            float a[8]  = {a0.x, a0.y, a0.z, a0.w, a1.x, a1.y, a1.z, a1.w};
            float bb[8] = {b0.x, b0.y, b0.z, b0.w, b1.x, b1.y, b1.z, b1.w};
#pragma unroll
            for (int i = 0; i < 8; i++)
#pragma unroll
                for (int j = 0; j < 8; j++)
                    acc[i][j] = fmaf(a[i], bb[j], acc[i][j]);
        }
        __syncthreads();
    }
}

// ===========================================================================
// y2[h][b][c] = d4[b,:] @ W_h[256:512,:]   grid NHEAD, block 256.
// ===========================================================================
__global__ void __launch_bounds__(256)
k_y2(const float* __restrict__ W) {
    int h = blockIdx.x;
    float acc[8][8];
    gemm_tile64<COMP, COMP>(g_d4, W + (size_t)h * 512 * 256 + 256 * 256, acc);
    int tid  = threadIdx.x;
    int rowb = (tid >> 5) << 3;
    int cb   = (tid & 31) << 2;
#pragma unroll
    for (int i = 0; i < 8; i++)
#pragma unroll
        for (int j = 0; j < 8; j++) {
            int c = (j < 4) ? cb + j : cb + 124 + j;
            g_y2[((size_t)h * 64 + rowb + i) * 256 + c] = acc[i][j];
        }
}

// ===========================================================================
// W^T split prep (k_att): g_Wth/l[h][c][k] = bf16 split of W[h][k][c], k<256.
// ===========================================================================
__global__ void __launch_bounds__(256)
k_wsplit(const float* __restrict__ W) {
    int h = blockIdx.x;
    for (int i = threadIdx.x; i < 256 * 256; i += 256) {
        int k = i >> 8, c = i & 255;
        float v = W[((size_t)h * 512 + k) * 256 + c];
        __nv_bfloat16 hi = __float2bfloat16_rn(v);
        __nv_bfloat16 lo = __float2bfloat16_rn(v - __bfloat162float(hi));
        size_t o = ((size_t)h * 256 + c) * 256 + k;
        g_Wth[o] = hi;
        g_Wtl[o] = lo;
    }
}

// ===========================================================================
// w1/wv transposed split (k_proj): g_wpth/l[path][c][k].  grid (64, 2).
// ===========================================================================
__global__ void __launch_bounds__(256)
k_wsplit2(const float* __restrict__ w1, const float* __restrict__ wv) {
    int path = blockIdx.y;
    const float* w = path ? wv : w1;
    for (int i = blockIdx.x * 256 + threadIdx.x; i < 256 * 512; i += 64 * 256) {
        int c = i >> 9, k = i & 511;
        float v = w[(size_t)k * 256 + c];
        __nv_bfloat16 hi = __float2bfloat16_rn(v);
        __nv_bfloat16 lo = __float2bfloat16_rn(v - __bfloat162float(hi));
        size_t o = ((size_t)path * 256 + c) * 512 + k;
        g_wpth[o] = hi;
        g_wptl[o] = lo;
    }
}

// ===========================================================================
// d2 bf16 split: g_d2p[row][256 hi | 256 lo] words.  grid 8192, block 256.
// ===========================================================================
__global__ void __launch_bounds__(256)
k_d2split(const float* __restrict__ d2) {
    const float2* src = (const float2*)d2;
    for (size_t p = (size_t)blockIdx.x * 256 + threadIdx.x;
         p < (size_t)SEQ * BATCH * 256; p += (size_t)8192 * 256) {
        size_t r = p >> 8;
        int j = (int)(p & 255);
        float2 v = src[p];
        uint32_t hi, lo;
        split2(v.x, v.y, hi, lo);
        g_d2p[r * 512 + j]       = hi;
        g_d2p[r * 512 + 256 + j] = lo;
    }
}

// ===========================================================================
// k_proj via HMMA bf16-split. grid (2 cx, 2 path, 256 mblk), block 256.
// CTA: D[128 rows][128 cols] over K=512 (8 chunks of 64).
// path 0 -> g_d3p (bias+relu+split), path 1 -> g_tv (tanh).
// Smem words: Ah 0, Al 4608, Bh 9216, Bl 13824 (pitch 36), b1s 18432.
// ===========================================================================
#define PROJ_SMEM_WORDS 18560
#define PROJ_SMEM_BYTES (PROJ_SMEM_WORDS * 4)

__global__ void __launch_bounds__(256, 2)
k_proj_mma(const float* __restrict__ b1) {
    extern __shared__ __align__(16) uint32_t sm[];
    uint32_t* Ah = sm;
    uint32_t* Al = sm + 4608;
    uint32_t* Bh = sm + 9216;
    uint32_t* Bl = sm + 13824;
    float*    b1s = (float*)(sm + 18432);

    const int cx = blockIdx.x, path = blockIdx.y, zb = blockIdx.z;
    const int m0 = zb * 128;
    const int tid = threadIdx.x;
    const int wid = tid >> 5;
    const int lane = tid & 31;
    const int g  = lane >> 2;
    const int tg = lane & 3;
    const int m0w = wid * 16;

    if (path == 0 && tid < 128) b1s[tid] = b1[cx * 128 + tid];

    float acc[16][4];
#pragma unroll
    for (int n8 = 0; n8 < 16; n8++)
#pragma unroll
        for (int e = 0; e < 4; e++) acc[n8][e] = 0.f;

    const __nv_bfloat16* Wh = g_wpth + ((size_t)path * 256 + cx * 128) * 512;
    const __nv_bfloat16* Wl = g_wptl + ((size_t)path * 256 + cx * 128) * 512;

    for (int ch = 0; ch < 8; ch++) {
        __syncthreads();
        // A chunk: 128 rows x 64 k, hi+lo
        for (int t = tid; t < 2048; t += 256) {
            int r = t >> 4, j = t & 15;
            int plane = j >> 3, kw = (j & 7) * 4;
            const uint4 v = *(const uint4*)(g_d2p + (size_t)(m0 + r) * 512 +
                                            plane * 256 + ch * 32 + kw);
            uint32_t* dstp = (plane ? Al : Ah) + r * 36 + kw;
            *(uint4*)dstp = v;
        }
        // B chunk: 128 cols x 64 k, hi+lo
        for (int t = tid; t < 2048; t += 256) {
            int n = t >> 4, j = t & 15;
            int plane = j >> 3, j8 = j & 7;
            const uint4* srow = (const uint4*)((plane ? Wl : Wh) + (size_t)n * 512 + ch * 64);
            uint32_t* dstp = (plane ? Bl : Bh) + n * 36 + j8 * 4;
            *(uint4*)dstp = srow[j8];
        }
        __syncthreads();

#pragma unroll
        for (int ks = 0; ks < 4; ks++) {
            const int kw0 = ks * 8;
            const int ra = (m0w + g) * 36 + kw0 + tg;
            const int rb = (m0w + g + 8) * 36 + kw0 + tg;
            uint32_t ah0 = Ah[ra],     ah1 = Ah[rb];
            uint32_t ah2 = Ah[ra + 4], ah3 = Ah[rb + 4];
            uint32_t al0 = Al[ra],     al1 = Al[rb];
            uint32_t al2 = Al[ra + 4], al3 = Al[rb + 4];
#pragma unroll
            for (int n8 = 0; n8 < 16; n8++) {
                const int nb = (n8 * 8 + g) * 36 + kw0 + tg;
                uint32_t b0 = Bh[nb], b1w = Bh[nb + 4];
                uint32_t c0 = Bl[nb], c1 = Bl[nb + 4];
                mma16816(acc[n8], ah0, ah1, ah2, ah3, b0, b1w);
                mma16816(acc[n8], ah0, ah1, ah2, ah3, c0, c1);
                mma16816(acc[n8], al0, al1, al2, al3, b0, b1w);
            }
        }
    }

    const int r0 = m0w + g, r1 = r0 + 8;
    const int R0 = m0 + r0, R1 = m0 + r1;
    if (path == 0) {
        uint32_t* dst0 = g_d3p + (size_t)R0 * 256;
        uint32_t* dst1 = g_d3p + (size_t)R1 * 256;
#pragma unroll
        for (int n8 = 0; n8 < 16; n8++) {
            const int cc = n8 * 8 + tg * 2;
            const int word = cx * 64 + n8 * 4 + tg;
            const float bb0 = b1s[cc], bb1 = b1s[cc + 1];
            uint32_t hi, lo;
            float v0 = fmaxf(acc[n8][0] + bb0, 0.f);
            float v1 = fmaxf(acc[n8][1] + bb1, 0.f);
            split2(v0, v1, hi, lo);
            dst0[word] = hi; dst0[128 + word] = lo;
            float v2 = fmaxf(acc[n8][2] + bb0, 0.f);
            float v3 = fmaxf(acc[n8][3] + bb1, 0.f);
            split2(v2, v3, hi, lo);
            dst1[word] = hi; dst1[128 + word] = lo;
        }
    } else {
        const int s0 = R0 >> 6, b0i = R0 & 63;
        const int s1 = R1 >> 6, b1i = R1 & 63;
        float* t0 = g_tv + ((size_t)b0i * 512 + s0) * 256 + cx * 128;
        float* t1 = g_tv + ((size_t)b1i * 512 + s1) * 256 + cx * 128;
#pragma unroll
        for (int n8 = 0; n8 < 16; n8++) {
            const int cc = n8 * 8 + tg * 2;
            *(float2*)(t0 + cc) = make_float2(tanhf(acc[n8][0]), tanhf(acc[n8][1]));
            *(float2*)(t1 + cc) = make_float2(tanhf(acc[n8][2]), tanhf(acc[n8][3]));
        }
    }
}

// ===========================================================================
// k_att via HMMA bf16-split (round-6 proven). grid (2 cx, 8 h, 256), blk 256.
// ===========================================================================
#define ATT_SMEM_WORDS 27008
#define ATT_SMEM_BYTES (ATT_SMEM_WORDS * 4)

__global__ void __launch_bounds__(256, 2)
k_att_mma(const float* __restrict__ P) {
    extern __shared__ __align__(16) uint32_t sm[];
    uint32_t* Ah = sm;
    uint32_t* Al = sm + 4608;
    uint32_t* Bh = sm + 9216;
    uint32_t* Bl = sm + 13824;
    float*    y2s = (float*)(sm + 18432);   // [b 0..63][pitch 132]
    float*    Ps  = (float*)(sm + 26880);

    const int cx = blockIdx.x, h = blockIdx.y, zb = blockIdx.z;
    const int m0 = zb * 128;
    const int tid = threadIdx.x;
    const int wid = tid >> 5;
    const int lane = tid & 31;
    const int g  = lane >> 2;
    const int tg = lane & 3;
    const int m0w = wid * 16;

    for (int i = tid; i < 8192; i += 256) {
        int b = i >> 7, cc = i & 127;
        y2s[b * 132 + cc] = g_y2[((size_t)h * 64 + b) * 256 + cx * 128 + cc];
    }
    if (tid < 128) Ps[tid] = P[h * 256 + cx * 128 + tid];

    float acc[16][4];
#pragma unroll
    for (int n8 = 0; n8 < 16; n8++)
#pragma unroll
        for (int e = 0; e < 4; e++) acc[n8][e] = 0.f;

    const __nv_bfloat16* Wh = g_Wth + ((size_t)h * 256 + cx * 128) * 256;
    const __nv_bfloat16* Wl = g_Wtl + ((size_t)h * 256 + cx * 128) * 256;

    for (int ch = 0; ch < 4; ch++) {
        const int kc0 = ch * 64;
        __syncthreads();
        for (int t = tid; t < 2048; t += 256) {
            int r = t >> 4, j = t & 15;
            int plane = j >> 3, kw = (j & 7) * 4;
            const uint4 v = *(const uint4*)(g_d3p + (size_t)(m0 + r) * 256 +
                                            plane * 128 + (kc0 >> 1) + kw);
            uint32_t* dstp = (plane ? Al : Ah) + r * 36 + kw;
            *(uint4*)dstp = v;
        }
        for (int t = tid; t < 2048; t += 256) {
            int n = t >> 4, j = t & 15;
            int plane = j >> 3, j8 = j & 7;
            const uint4* srow = (const uint4*)((plane ? Wl : Wh) + (size_t)n * 256 + kc0);
            uint32_t* dstp = (plane ? Bl : Bh) + n * 36 + j8 * 4;
            *(uint4*)dstp = srow[j8];
        }
        __syncthreads();

#pragma unroll
        for (int ks = 0; ks < 4; ks++) {
            const int kw0 = ks * 8;
            const int ra = (m0w + g) * 36 + kw0 + tg;
            const int rb = (m0w + g + 8) * 36 + kw0 + tg;
            uint32_t ah0 = Ah[ra],     ah1 = Ah[rb];
            uint32_t ah2 = Ah[ra + 4], ah3 = Ah[rb + 4];
            uint32_t al0 = Al[ra],     al1 = Al[rb];
            uint32_t al2 = Al[ra + 4], al3 = Al[rb + 4];
#pragma unroll
            for (int n8 = 0; n8 < 16; n8++) {
                const int nb = (n8 * 8 + g) * 36 + kw0 + tg;
                uint32_t b0 = Bh[nb], b1 = Bh[nb + 4];
                uint32_t c0 = Bl[nb], c1 = Bl[nb + 4];
                mma16816(acc[n8], ah0, ah1, ah2, ah3, b0, b1);
                mma16816(acc[n8], ah0, ah1, ah2, ah3, c0, c1);
                mma16816(acc[n8], al0, al1, al2, al3, b0, b1);
            }
        }
    }

    const int r0 = m0w + g, r1 = r0 + 8;
    const int b0 = (m0 + r0) & 63, b1v = (m0 + r1) & 63;
    float ps0 = 0.f, ps1 = 0.f;
#pragma unroll
    for (int n8 = 0; n8 < 16; n8++) {
        const int cc0 = n8 * 8 + tg * 2;
        const float p0 = Ps[cc0], p1 = Ps[cc0 + 1];
        ps0 += tanhf(acc[n8][0] + y2s[b0 * 132 + cc0]) * p0
             + tanhf(acc[n8][1] + y2s[b0 * 132 + cc0 + 1]) * p1;
        ps1 += tanhf(acc[n8][2] + y2s[b1v * 132 + cc0]) * p0
             + tanhf(acc[n8][3] + y2s[b1v * 132 + cc0 + 1]) * p1;
    }
    ps0 += __shfl_xor_sync(0xffffffffu, ps0, 1);
    ps0 += __shfl_xor_sync(0xffffffffu, ps0, 2);
    ps1 += __shfl_xor_sync(0xffffffffu, ps1, 1);
    ps1 += __shfl_xor_sync(0xffffffffu, ps1, 2);
    if (tg == 0) {
        float* dst = g_attsp + (size_t)cx * (NHEAD * BATCH * SEQ);
        const int R0 = m0 + r0, R1 = m0 + r1;
        dst[((size_t)h * 64 + (R0 & 63)) * 512 + (R0 >> 6)] = ps0;
        dst[((size_t)h * 64 + (R1 & 63)) * 512 + (R1 >> 6)] = ps1;
    }
}

// ===========================================================================
// Row softmax over S=512, summing the two c-half partials. grid 512, blk 256.
// ===========================================================================
__global__ void k_softmax() {
    __shared__ float red[256];
    int row = blockIdx.x, tid = threadIdx.x;
    const float* a0 = g_attsp + (size_t)row * 512;
    const float* a1 = a0 + (size_t)NHEAD * BATCH * SEQ;
    float v0 = a0[tid] + a1[tid];
    float v1 = a0[tid + 256] + a1[tid + 256];
    red[tid] = fmaxf(v0, v1);
    __syncthreads();
    for (int o = 128; o > 0; o >>= 1) {
        if (tid < o) red[tid] = fmaxf(red[tid], red[tid + o]);
        __syncthreads();
    }
    float m = red[0];
    __syncthreads();
    float e0 = expf(v0 - m), e1 = expf(v1 - m);
    red[tid] = e0 + e1;
    __syncthreads();
    for (int o = 128; o > 0; o >>= 1) {
        if (tid < o) red[tid] += red[tid + o];
        __syncthreads();
    }
    float inv = 1.f / red[0];
    g_scores[(size_t)row * 512 + tid]       = e0 * inv;
    g_scores[(size_t)row * 512 + tid + 256] = e1 * inv;
}

// ===========================================================================
// Partial vs over s-chunks. grid (BATCH, 8), block 256.
// ===========================================================================
__global__ void __launch_bounds__(256)
k_out1() {
    __shared__ float sc[512];
    int b = blockIdx.x, sb = blockIdx.y, tid = threadIdx.x;
    for (int i = tid; i < 512; i += 256) {
        int h = i >> 6, ss = i & 63;
        sc[i] = g_scores[((size_t)h * 64 + b) * 512 + sb * 64 + ss];
    }
    __syncthreads();
    float acc[NHEAD] = {0.f, 0.f, 0.f, 0.f, 0.f, 0.f, 0.f, 0.f};
    const float* tvb = g_tv + ((size_t)b * 512 + sb * 64) * 256 + tid;
    for (int ss = 0; ss < 64; ss++) {
        float t = tvb[(size_t)ss * 256];
#pragma unroll
        for (int h = 0; h < NHEAD; h++) acc[h] = fmaf(sc[h * 64 + ss], t, acc[h]);
    }
#pragma unroll
    for (int h = 0; h < NHEAD; h++)
        g_vsp[((size_t)sb * 64 + b) * 2048 + h * 256 + tid] = acc[h];
}

// ===========================================================================
// Reduce partials + final cc. grid 64, block 128.
// ===========================================================================
__global__ void __launch_bounds__(128)
k_out2(const float* __restrict__ wcc, const float* __restrict__ bcc,
       float* __restrict__ out) {
    __shared__ float vsf[2048];
    int b = blockIdx.x, tid = threadIdx.x;
    for (int i = tid; i < 2048; i += 128) {
        float v = 0.f;
#pragma unroll
        for (int sb = 0; sb < 8; sb++)
            v += g_vsp[((size_t)sb * 64 + b) * 2048 + i];
        vsf[i] = v;
    }
    __syncthreads();
    float o = bcc[tid];
#pragma unroll 8
    for (int i = 0; i < 2048; i++) o = fmaf(vsf[i], wcc[i * 128 + tid], o);
    out[b * 128 + tid] = fmaxf(o, 0.f);
}

// ===========================================================================
extern "C" void kernel_launch(void* const* d_in, const int* in_sizes, int n_in,
                              void* d_out, int out_size) {
    const float* d1  = (const float*)d_in[0];
    const float* d2  = (const float*)d_in[1];
    const float* w1  = (const float*)d_in[2];
    const float* b1  = (const float*)d_in[3];
    const float* W   = (const float*)d_in[4];
    const float* P   = (const float*)d_in[5];
    const float* wv  = (const float*)d_in[6];
    const float* wcc = (const float*)d_in[7];
    const float* bcc = (const float*)d_in[8];
    float* out = (float*)d_out;

    cudaFuncSetAttribute(k_att_mma, cudaFuncAttributeMaxDynamicSharedMemorySize,
                         ATT_SMEM_BYTES);
    cudaFuncSetAttribute(k_proj_mma, cudaFuncAttributeMaxDynamicSharedMemorySize,
                         PROJ_SMEM_BYTES);

    k_d4<<<BATCH, COMP>>>(d1, w1, b1);
    k_y2<<<NHEAD, 256>>>(W);
    k_wsplit<<<NHEAD, 256>>>(W);
    k_wsplit2<<<dim3(64, 2), 256>>>(w1, wv);
    k_d2split<<<8192, 256>>>(d2);
    k_proj_mma<<<dim3(2, 2, 256), 256, PROJ_SMEM_BYTES>>>(b1);
    k_att_mma<<<dim3(2, NHEAD, SEQ / 2), 256, ATT_SMEM_BYTES>>>(P);
    k_softmax<<<NHEAD * BATCH, 256>>>();
    k_out1<<<dim3(BATCH, 8), 256>>>();
    k_out2<<<BATCH, 128>>>(wcc, bcc, out);
}

// round 8
// speedup vs baseline: 1.6117x; 1.0961x over previous
#include <cuda_runtime.h>
#include <cuda_bf16.h>
#include <cstdint>

#define SEQ   512
#define BATCH 64
#define FEAT  512
#define COMP  256
#define NHEAD 8

// Scratch (allocation-free rule: __device__ globals)
__device__ uint32_t g_d3p[(size_t)SEQ * BATCH * 256];   // d3 bf16 split: [row][128 hi | 128 lo] words
__device__ float g_tv[(size_t)BATCH * SEQ * COMP];      // [64][512][256]
__device__ float g_d4[BATCH * COMP];                    // [64][256]
__device__ float g_y2[NHEAD * BATCH * COMP];            // [8][64][256]
__device__ float g_attsp[2 * NHEAD * BATCH * SEQ];      // two c-half partials
__device__ float g_scores[NHEAD * BATCH * SEQ];
__device__ float g_vsp[8 * BATCH * NHEAD * COMP];       // [8 sb][64][2048]
// W^T bf16 split for k_att: [h][c][k<256]
__device__ __align__(16) __nv_bfloat16 g_Wth[NHEAD * 256 * 256];
__device__ __align__(16) __nv_bfloat16 g_Wtl[NHEAD * 256 * 256];
// w1/wv transposed split for k_proj: [path][c][k<512]
__device__ __align__(16) __nv_bfloat16 g_wpth[2 * 256 * 512];
__device__ __align__(16) __nv_bfloat16 g_wptl[2 * 256 * 512];

__device__ __forceinline__ uint32_t smem_u32(const void* p) {
    uint32_t a;
    asm("{ .reg .u64 t; cvta.to.shared.u64 t, %1; cvt.u32.u64 %0, t; }" : "=r"(a) : "l"(p));
    return a;
}

// bf16 split of a pair of floats -> packed hi and lo words
__device__ __forceinline__ void split2(float a, float b, uint32_t& hi, uint32_t& lo) {
    __nv_bfloat16 ha = __float2bfloat16_rn(a);
    __nv_bfloat16 hb = __float2bfloat16_rn(b);
    __nv_bfloat16 la = __float2bfloat16_rn(a - __bfloat162float(ha));
    __nv_bfloat16 lb = __float2bfloat16_rn(b - __bfloat162float(hb));
    hi = (uint32_t)__bfloat16_as_ushort(ha) | ((uint32_t)__bfloat16_as_ushort(hb) << 16);
    lo = (uint32_t)__bfloat16_as_ushort(la) | ((uint32_t)__bfloat16_as_ushort(lb) << 16);
}

__device__ __forceinline__ void mma16816(float c[4], const uint32_t a[4],
                                         uint32_t b0, uint32_t b1) {
    asm volatile(
        "mma.sync.aligned.m16n8k16.row.col.f32.bf16.bf16.f32 "
        "{%0,%1,%2,%3}, {%4,%5,%6,%7}, {%8,%9}, {%0,%1,%2,%3};"
        : "+f"(c[0]), "+f"(c[1]), "+f"(c[2]), "+f"(c[3])
        : "r"(a[0]), "r"(a[1]), "r"(a[2]), "r"(a[3]), "r"(b0), "r"(b1));
}

__device__ __forceinline__ void ldsm_x4(uint32_t r[4], uint32_t addr) {
    asm volatile("ldmatrix.sync.aligned.m8n8.x4.shared.b16 {%0,%1,%2,%3}, [%4];"
        : "=r"(r[0]), "=r"(r[1]), "=r"(r[2]), "=r"(r[3]) : "r"(addr));
}

// ===========================================================================
// d4 = relu(d1 @ w1 + b1)   [64,256]
// ===========================================================================
__global__ void k_d4(const float* __restrict__ d1, const float* __restrict__ w1,
                     const float* __restrict__ b1) {
    __shared__ float row[FEAT];
    int b = blockIdx.x, c = threadIdx.x;
    for (int i = c; i < FEAT; i += blockDim.x) row[i] = d1[b * FEAT + i];
    __syncthreads();
    float acc = b1[c];
#pragma unroll 8
    for (int d = 0; d < FEAT; d++) acc = fmaf(row[d], w1[d * COMP + c], acc);
    g_d4[b * COMP + c] = fmaxf(acc, 0.f);
}

// ===========================================================================
// 64-row fp32 tile GEMM (round-2 proven). 256 threads, 8x8 microtile.
// ===========================================================================
template <int K, int LDA>
__device__ __forceinline__ void gemm_tile64(const float* __restrict__ A,
                                            const float* __restrict__ Bm,
                                            float acc[8][8]) {
    __shared__ float As[16 * 64];
    __shared__ float Bs[16 * 256];
    int tid  = threadIdx.x;
    int am   = tid >> 2;
    int ak   = (tid & 3) << 2;
    int bn   = (tid & 63) << 2;
    int bk   = (tid >> 6) << 2;
    int rowb = (tid >> 5) << 3;
    int cb   = (tid & 31) << 2;

#pragma unroll
    for (int i = 0; i < 8; i++)
#pragma unroll
        for (int j = 0; j < 8; j++) acc[i][j] = 0.f;

    for (int k0 = 0; k0 < K; k0 += 16) {
        float4 av = *(const float4*)(A + am * LDA + k0 + ak);
        As[(ak + 0) * 64 + am] = av.x;
        As[(ak + 1) * 64 + am] = av.y;
        As[(ak + 2) * 64 + am] = av.z;
        As[(ak + 3) * 64 + am] = av.w;
#pragma unroll
        for (int i = 0; i < 4; i++) {
            *(float4*)(Bs + (bk + i) * 256 + bn) =
                *(const float4*)(Bm + (size_t)(k0 + bk + i) * 256 + bn);
        }
        __syncthreads();
#pragma unroll
        for (int kk = 0; kk < 16; kk++) {
            float4 a0 = *(const float4*)(As + kk * 64 + rowb);
            float4 a1 = *(const float4*)(As + kk * 64 + rowb + 4);
            float4 b0 = *(const float4*)(Bs + kk * 256 + cb);
            float4 b1 = *(const float4*)(Bs + kk * 256 + cb + 128);
            float a[8]  = {a0.x, a0.y, a0.z, a0.w, a1.x, a1.y, a1.z, a1.w};
            float bb[8] = {b0.x, b0.y, b0.z, b0.w, b1.x, b1.y, b1.z, b1.w};
#pragma unroll
            for (int i = 0; i < 8; i++)
#pragma unroll
                for (int j = 0; j < 8; j++)
                    acc[i][j] = fmaf(a[i], bb[j], acc[i][j]);
        }
        __syncthreads();
    }
}

// ===========================================================================
// y2[h][b][c] = d4[b,:] @ W_h[256:512,:]   grid NHEAD, block 256.
// ===========================================================================
__global__ void __launch_bounds__(256)
k_y2(const float* __restrict__ W) {
    int h = blockIdx.x;
    float acc[8][8];
    gemm_tile64<COMP, COMP>(g_d4, W + (size_t)h * 512 * 256 + 256 * 256, acc);
    int tid  = threadIdx.x;
    int rowb = (tid >> 5) << 3;
    int cb   = (tid & 31) << 2;
#pragma unroll
    for (int i = 0; i < 8; i++)
#pragma unroll
        for (int j = 0; j < 8; j++) {
            int c = (j < 4) ? cb + j : cb + 124 + j;
            g_y2[((size_t)h * 64 + rowb + i) * 256 + c] = acc[i][j];
        }
}

// ===========================================================================
// Weight split prep (fused): blocks 0..7 -> W^T split (k_att);
// blocks 8..9 -> w1/wv transposed split (k_proj). grid 10, block 256.
// ===========================================================================
__global__ void __launch_bounds__(256)
k_wsplit(const float* __restrict__ W, const float* __restrict__ w1,
         const float* __restrict__ wv) {
    if (blockIdx.x < 8) {
        int h = blockIdx.x;
        for (int i = threadIdx.x; i < 256 * 256; i += 256) {
            int k = i >> 8, c = i & 255;
            float v = W[((size_t)h * 512 + k) * 256 + c];
            __nv_bfloat16 hi = __float2bfloat16_rn(v);
            __nv_bfloat16 lo = __float2bfloat16_rn(v - __bfloat162float(hi));
            size_t o = ((size_t)h * 256 + c) * 256 + k;
            g_Wth[o] = hi;
            g_Wtl[o] = lo;
        }
    } else {
        int path = blockIdx.x - 8;
        const float* w = path ? wv : w1;
        for (int i = threadIdx.x; i < 256 * 512; i += 256) {
            int c = i >> 9, k = i & 511;
            float v = w[(size_t)k * 256 + c];
            __nv_bfloat16 hi = __float2bfloat16_rn(v);
            __nv_bfloat16 lo = __float2bfloat16_rn(v - __bfloat162float(hi));
            size_t o = ((size_t)path * 256 + c) * 512 + k;
            g_wpth[o] = hi;
            g_wptl[o] = lo;
        }
    }
}

// ===========================================================================
// k_proj via HMMA bf16-split + ldmatrix. grid (2 cx, 2 path, 256 mblk), blk 256.
// CTA: D[128 rows][128 cols] over K=512 (8 chunks of 64). A converted from
// fp32 d2 inline while staging to smem.
// path 0 -> g_d3p (bias+relu+split), path 1 -> g_tv (tanh).
// Smem words: Ah 0, Al 4608, Bh 9216, Bl 13824 (pitch 36), b1s 18432.
// ===========================================================================
#define PROJ_SMEM_WORDS 18560
#define PROJ_SMEM_BYTES (PROJ_SMEM_WORDS * 4)

__global__ void __launch_bounds__(256, 2)
k_proj_mma(const float* __restrict__ d2, const float* __restrict__ b1) {
    extern __shared__ __align__(16) uint32_t sm[];
    uint32_t* Ah = sm;
    uint32_t* Al = sm + 4608;
    uint32_t* Bh = sm + 9216;
    uint32_t* Bl = sm + 13824;
    float*    b1s = (float*)(sm + 18432);

    const int cx = blockIdx.x, path = blockIdx.y, zb = blockIdx.z;
    const int m0 = zb * 128;
    const int tid = threadIdx.x;
    const int wid = tid >> 5;
    const int lane = tid & 31;
    const int g  = lane >> 2;
    const int tg = lane & 3;
    const int m0w = wid * 16;

    if (path == 0 && tid < 128) b1s[tid] = b1[cx * 128 + tid];

    // ldmatrix per-lane base addresses (bytes)
    const uint32_t smb = smem_u32(sm);
    const int arow = m0w + (lane & 7) + ((lane >> 3) & 1) * 8;
    const int akoff = (lane >> 4) * 4;
    const uint32_t aaddr_h = smb + (uint32_t)(arow * 36 + akoff) * 4;
    const uint32_t aaddr_l = aaddr_h + 4608u * 4;
    const int brow = (lane & 7) + ((lane >> 4) << 3);
    const int bkoff = ((lane >> 3) & 1) * 4;
    const uint32_t baddr_h = smb + (uint32_t)(9216 + brow * 36 + bkoff) * 4;
    const uint32_t baddr_l = baddr_h + 4608u * 4;

    float acc[16][4];
#pragma unroll
    for (int n8 = 0; n8 < 16; n8++)
#pragma unroll
        for (int e = 0; e < 4; e++) acc[n8][e] = 0.f;

    const __nv_bfloat16* Wh = g_wpth + ((size_t)path * 256 + cx * 128) * 512;
    const __nv_bfloat16* Wl = g_wptl + ((size_t)path * 256 + cx * 128) * 512;

    for (int ch = 0; ch < 8; ch++) {
        __syncthreads();
        // A chunk: fp32 -> bf16 hi/lo split inline (128 rows x 64 k)
        for (int t = tid; t < 2048; t += 256) {
            int r = t >> 4, j = t & 15;
            float4 v = *(const float4*)(d2 + (size_t)(m0 + r) * 512 + ch * 64 + j * 4);
            uint32_t hi0, lo0, hi1, lo1;
            split2(v.x, v.y, hi0, lo0);
            split2(v.z, v.w, hi1, lo1);
            Ah[r * 36 + j * 2]     = hi0;
            Ah[r * 36 + j * 2 + 1] = hi1;
            Al[r * 36 + j * 2]     = lo0;
            Al[r * 36 + j * 2 + 1] = lo1;
        }
        // B chunk: 128 cols x 64 k, hi+lo
        for (int t = tid; t < 2048; t += 256) {
            int n = t >> 4, j = t & 15;
            int plane = j >> 3, j8 = j & 7;
            const uint4* srow = (const uint4*)((plane ? Wl : Wh) + (size_t)n * 512 + ch * 64);
            uint32_t* dstp = (plane ? Bl : Bh) + n * 36 + j8 * 4;
            *(uint4*)dstp = srow[j8];
        }
        __syncthreads();

#pragma unroll
        for (int ks = 0; ks < 4; ks++) {
            const uint32_t kb = (uint32_t)(ks * 8) * 4;
            uint32_t ah[4], al[4];
            ldsm_x4(ah, aaddr_h + kb);
            ldsm_x4(al, aaddr_l + kb);
#pragma unroll
            for (int p = 0; p < 8; p++) {
                uint32_t bh[4], bl[4];
                const uint32_t bo = (uint32_t)(p * 16 * 36) * 4 + kb;
                ldsm_x4(bh, baddr_h + bo);
                ldsm_x4(bl, baddr_l + bo);
                mma16816(acc[2 * p],     ah, bh[0], bh[1]);
                mma16816(acc[2 * p],     ah, bl[0], bl[1]);
                mma16816(acc[2 * p],     al, bh[0], bh[1]);
                mma16816(acc[2 * p + 1], ah, bh[2], bh[3]);
                mma16816(acc[2 * p + 1], ah, bl[2], bl[3]);
                mma16816(acc[2 * p + 1], al, bh[2], bh[3]);
            }
        }
    }

    const int r0 = m0w + g, r1 = r0 + 8;
    const int R0 = m0 + r0, R1 = m0 + r1;
    if (path == 0) {
        uint32_t* dst0 = g_d3p + (size_t)R0 * 256;
        uint32_t* dst1 = g_d3p + (size_t)R1 * 256;
#pragma unroll
        for (int n8 = 0; n8 < 16; n8++) {
            const int cc = n8 * 8 + tg * 2;
            const int word = cx * 64 + n8 * 4 + tg;
            const float bb0 = b1s[cc], bb1 = b1s[cc + 1];
            uint32_t hi, lo;
            float v0 = fmaxf(acc[n8][0] + bb0, 0.f);
            float v1 = fmaxf(acc[n8][1] + bb1, 0.f);
            split2(v0, v1, hi, lo);
            dst0[word] = hi; dst0[128 + word] = lo;
            float v2 = fmaxf(acc[n8][2] + bb0, 0.f);
            float v3 = fmaxf(acc[n8][3] + bb1, 0.f);
            split2(v2, v3, hi, lo);
            dst1[word] = hi; dst1[128 + word] = lo;
        }
    } else {
        const int s0 = R0 >> 6, b0i = R0 & 63;
        const int s1 = R1 >> 6, b1i = R1 & 63;
        float* t0 = g_tv + ((size_t)b0i * 512 + s0) * 256 + cx * 128;
        float* t1 = g_tv + ((size_t)b1i * 512 + s1) * 256 + cx * 128;
#pragma unroll
        for (int n8 = 0; n8 < 16; n8++) {
            const int cc = n8 * 8 + tg * 2;
            *(float2*)(t0 + cc) = make_float2(tanhf(acc[n8][0]), tanhf(acc[n8][1]));
            *(float2*)(t1 + cc) = make_float2(tanhf(acc[n8][2]), tanhf(acc[n8][3]));
        }
    }
}

// ===========================================================================
// k_att via HMMA bf16-split + ldmatrix. grid (2 cx, 8 h, 256), blk 256.
// ===========================================================================
#define ATT_SMEM_WORDS 27008
#define ATT_SMEM_BYTES (ATT_SMEM_WORDS * 4)

__global__ void __launch_bounds__(256, 2)
k_att_mma(const float* __restrict__ P) {
    extern __shared__ __align__(16) uint32_t sm[];
    uint32_t* Ah = sm;
    uint32_t* Al = sm + 4608;
    uint32_t* Bh = sm + 9216;
    uint32_t* Bl = sm + 13824;
    float*    y2s = (float*)(sm + 18432);   // [b 0..63][pitch 132]
    float*    Ps  = (float*)(sm + 26880);

    const int cx = blockIdx.x, h = blockIdx.y, zb = blockIdx.z;
    const int m0 = zb * 128;
    const int tid = threadIdx.x;
    const int wid = tid >> 5;
    const int lane = tid & 31;
    const int g  = lane >> 2;
    const int tg = lane & 3;
    const int m0w = wid * 16;

    for (int i = tid; i < 8192; i += 256) {
        int b = i >> 7, cc = i & 127;
        y2s[b * 132 + cc] = g_y2[((size_t)h * 64 + b) * 256 + cx * 128 + cc];
    }
    if (tid < 128) Ps[tid] = P[h * 256 + cx * 128 + tid];

    const uint32_t smb = smem_u32(sm);
    const int arow = m0w + (lane & 7) + ((lane >> 3) & 1) * 8;
    const int akoff = (lane >> 4) * 4;
    const uint32_t aaddr_h = smb + (uint32_t)(arow * 36 + akoff) * 4;
    const uint32_t aaddr_l = aaddr_h + 4608u * 4;
    const int brow = (lane & 7) + ((lane >> 4) << 3);
    const int bkoff = ((lane >> 3) & 1) * 4;
    const uint32_t baddr_h = smb + (uint32_t)(9216 + brow * 36 + bkoff) * 4;
    const uint32_t baddr_l = baddr_h + 4608u * 4;

    float acc[16][4];
#pragma unroll
    for (int n8 = 0; n8 < 16; n8++)
#pragma unroll
        for (int e = 0; e < 4; e++) acc[n8][e] = 0.f;

    const __nv_bfloat16* Wh = g_Wth + ((size_t)h * 256 + cx * 128) * 256;
    const __nv_bfloat16* Wl = g_Wtl + ((size_t)h * 256 + cx * 128) * 256;

    for (int ch = 0; ch < 4; ch++) {
        const int kc0 = ch * 64;
        __syncthreads();
        for (int t = tid; t < 2048; t += 256) {
            int r = t >> 4, j = t & 15;
            int plane = j >> 3, kw = (j & 7) * 4;
            const uint4 v = *(const uint4*)(g_d3p + (size_t)(m0 + r) * 256 +
                                            plane * 128 + (kc0 >> 1) + kw);
            uint32_t* dstp = (plane ? Al : Ah) + r * 36 + kw;
            *(uint4*)dstp = v;
        }
        for (int t = tid; t < 2048; t += 256) {
            int n = t >> 4, j = t & 15;
            int plane = j >> 3, j8 = j & 7;
            const uint4* srow = (const uint4*)((plane ? Wl : Wh) + (size_t)n * 256 + kc0);
            uint32_t* dstp = (plane ? Bl : Bh) + n * 36 + j8 * 4;
            *(uint4*)dstp = srow[j8];
        }
        __syncthreads();

#pragma unroll
        for (int ks = 0; ks < 4; ks++) {
            const uint32_t kb = (uint32_t)(ks * 8) * 4;
            uint32_t ah[4], al[4];
            ldsm_x4(ah, aaddr_h + kb);
            ldsm_x4(al, aaddr_l + kb);
#pragma unroll
            for (int p = 0; p < 8; p++) {
                uint32_t bh[4], bl[4];
                const uint32_t bo = (uint32_t)(p * 16 * 36) * 4 + kb;
                ldsm_x4(bh, baddr_h + bo);
                ldsm_x4(bl, baddr_l + bo);
                mma16816(acc[2 * p],     ah, bh[0], bh[1]);
                mma16816(acc[2 * p],     ah, bl[0], bl[1]);
                mma16816(acc[2 * p],     al, bh[0], bh[1]);
                mma16816(acc[2 * p + 1], ah, bh[2], bh[3]);
                mma16816(acc[2 * p + 1], ah, bl[2], bl[3]);
                mma16816(acc[2 * p + 1], al, bh[2], bh[3]);
            }
        }
    }

    const int r0 = m0w + g, r1 = r0 + 8;
    const int b0 = (m0 + r0) & 63, b1v = (m0 + r1) & 63;
    float ps0 = 0.f, ps1 = 0.f;
#pragma unroll
    for (int n8 = 0; n8 < 16; n8++) {
        const int cc0 = n8 * 8 + tg * 2;
        const float p0 = Ps[cc0], p1 = Ps[cc0 + 1];
        ps0 += tanhf(acc[n8][0] + y2s[b0 * 132 + cc0]) * p0
             + tanhf(acc[n8][1] + y2s[b0 * 132 + cc0 + 1]) * p1;
        ps1 += tanhf(acc[n8][2] + y2s[b1v * 132 + cc0]) * p0
             + tanhf(acc[n8][3] + y2s[b1v * 132 + cc0 + 1]) * p1;
    }
    ps0 += __shfl_xor_sync(0xffffffffu, ps0, 1);
    ps0 += __shfl_xor_sync(0xffffffffu, ps0, 2);
    ps1 += __shfl_xor_sync(0xffffffffu, ps1, 1);
    ps1 += __shfl_xor_sync(0xffffffffu, ps1, 2);
    if (tg == 0) {
        float* dst = g_attsp + (size_t)cx * (NHEAD * BATCH * SEQ);
        const int R0 = m0 + r0, R1 = m0 + r1;
        dst[((size_t)h * 64 + (R0 & 63)) * 512 + (R0 >> 6)] = ps0;
        dst[((size_t)h * 64 + (R1 & 63)) * 512 + (R1 >> 6)] = ps1;
    }
}

// ===========================================================================
// Row softmax over S=512, summing the two c-half partials. grid 512, blk 256.
// ===========================================================================
__global__ void k_softmax() {
    __shared__ float red[256];
    int row = blockIdx.x, tid = threadIdx.x;
    const float* a0 = g_attsp + (size_t)row * 512;
    const float* a1 = a0 + (size_t)NHEAD * BATCH * SEQ;
    float v0 = a0[tid] + a1[tid];
    float v1 = a0[tid + 256] + a1[tid + 256];
    red[tid] = fmaxf(v0, v1);
    __syncthreads();
    for (int o = 128; o > 0; o >>= 1) {
        if (tid < o) red[tid] = fmaxf(red[tid], red[tid + o]);
        __syncthreads();
    }
    float m = red[0];
    __syncthreads();
    float e0 = expf(v0 - m), e1 = expf(v1 - m);
    red[tid] = e0 + e1;
    __syncthreads();
    for (int o = 128; o > 0; o >>= 1) {
        if (tid < o) red[tid] += red[tid + o];
        __syncthreads();
    }
    float inv = 1.f / red[0];
    g_scores[(size_t)row * 512 + tid]       = e0 * inv;
    g_scores[(size_t)row * 512 + tid + 256] = e1 * inv;
}

// ===========================================================================
// Partial vs over s-chunks. grid (BATCH, 8), block 256.
// ===========================================================================
__global__ void __launch_bounds__(256)
k_out1() {
    __shared__ float sc[512];
    int b = blockIdx.x, sb = blockIdx.y, tid = threadIdx.x;
    for (int i = tid; i < 512; i += 256) {
        int h = i >> 6, ss = i & 63;
        sc[i] = g_scores[((size_t)h * 64 + b) * 512 + sb * 64 + ss];
    }
    __syncthreads();
    float acc[NHEAD] = {0.f, 0.f, 0.f, 0.f, 0.f, 0.f, 0.f, 0.f};
    const float* tvb = g_tv + ((size_t)b * 512 + sb * 64) * 256 + tid;
#pragma unroll 8
    for (int ss = 0; ss < 64; ss++) {
        float t = tvb[(size_t)ss * 256];
#pragma unroll
        for (int h = 0; h < NHEAD; h++) acc[h] = fmaf(sc[h * 64 + ss], t, acc[h]);
    }
#pragma unroll
    for (int h = 0; h < NHEAD; h++)
        g_vsp[((size_t)sb * 64 + b) * 2048 + h * 256 + tid] = acc[h];
}

// ===========================================================================
// Reduce partials + final cc. grid 64, block 128.
// ===========================================================================
__global__ void __launch_bounds__(128)
k_out2(const float* __restrict__ wcc, const float* __restrict__ bcc,
       float* __restrict__ out) {
    __shared__ float vsf[2048];
    int b = blockIdx.x, tid = threadIdx.x;
    for (int i = tid; i < 2048; i += 128) {
        float v = 0.f;
#pragma unroll
        for (int sb = 0; sb < 8; sb++)
            v += g_vsp[((size_t)sb * 64 + b) * 2048 + i];
        vsf[i] = v;
    }
    __syncthreads();
    float o = bcc[tid];
#pragma unroll 8
    for (int i = 0; i < 2048; i++) o = fmaf(vsf[i], wcc[i * 128 + tid], o);
    out[b * 128 + tid] = fmaxf(o, 0.f);
}

// ===========================================================================
extern "C" void kernel_launch(void* const* d_in, const int* in_sizes, int n_in,
                              void* d_out, int out_size) {
    const float* d1  = (const float*)d_in[0];
    const float* d2  = (const float*)d_in[1];
    const float* w1  = (const float*)d_in[2];
    const float* b1  = (const float*)d_in[3];
    const float* W   = (const float*)d_in[4];
    const float* P   = (const float*)d_in[5];
    const float* wv  = (const float*)d_in[6];
    const float* wcc = (const float*)d_in[7];
    const float* bcc = (const float*)d_in[8];
    float* out = (float*)d_out;

    cudaFuncSetAttribute(k_att_mma, cudaFuncAttributeMaxDynamicSharedMemorySize,
                         ATT_SMEM_BYTES);
    cudaFuncSetAttribute(k_proj_mma, cudaFuncAttributeMaxDynamicSharedMemorySize,
                         PROJ_SMEM_BYTES);

    k_d4<<<BATCH, COMP>>>(d1, w1, b1);
    k_y2<<<NHEAD, 256>>>(W);
    k_wsplit<<<10, 256>>>(W, w1, wv);
    k_proj_mma<<<dim3(2, 2, 256), 256, PROJ_SMEM_BYTES>>>(d2, b1);
    k_att_mma<<<dim3(2, NHEAD, SEQ / 2), 256, ATT_SMEM_BYTES>>>(P);
    k_softmax<<<NHEAD * BATCH, 256>>>();
    k_out1<<<dim3(BATCH, 8), 256>>>();
    k_out2<<<BATCH, 128>>>(wcc, bcc, out);
}

// round 9
// speedup vs baseline: 1.6241x; 1.0077x over previous
#include <cuda_runtime.h>
#include <cuda_bf16.h>
#include <cstdint>

#define SEQ   512
#define BATCH 64
#define FEAT  512
#define COMP  256
#define NHEAD 8

// Scratch (allocation-free rule: __device__ globals)
__device__ uint32_t g_d3p[(size_t)SEQ * BATCH * 256];   // d3 bf16 split: [row][128 hi | 128 lo] words
__device__ float g_tv[(size_t)BATCH * SEQ * COMP];      // [64][512][256]
__device__ float g_d4[BATCH * COMP];                    // [64][256]
__device__ float g_y2[NHEAD * BATCH * COMP];            // [8][64][256]
__device__ float g_attsp[2 * NHEAD * BATCH * SEQ];      // two c-half partials
__device__ float g_scores[NHEAD * BATCH * SEQ];
__device__ float g_vsp[8 * BATCH * NHEAD * COMP];       // [8 sb][64][2048]
// W^T bf16 split for k_att: [h][c][k<256]
__device__ __align__(16) __nv_bfloat16 g_Wth[NHEAD * 256 * 256];
__device__ __align__(16) __nv_bfloat16 g_Wtl[NHEAD * 256 * 256];
// w1/wv transposed split for k_proj: [path][c][k<512]
__device__ __align__(16) __nv_bfloat16 g_wpth[2 * 256 * 512];
__device__ __align__(16) __nv_bfloat16 g_wptl[2 * 256 * 512];

__device__ __forceinline__ uint32_t smem_u32(const void* p) {
    uint32_t a;
    asm("{ .reg .u64 t; cvta.to.shared.u64 t, %1; cvt.u32.u64 %0, t; }" : "=r"(a) : "l"(p));
    return a;
}

#define CP16(dst, src) \
    asm volatile("cp.async.ca.shared.global [%0], [%1], 16;" :: "r"(dst), "l"(src) : "memory")
#define CP_COMMIT() asm volatile("cp.async.commit_group;" ::: "memory")
#define CP_WAIT(n)  asm volatile("cp.async.wait_group %0;" :: "n"(n) : "memory")

// bf16 split of a pair of floats -> packed hi and lo words
__device__ __forceinline__ void split2(float a, float b, uint32_t& hi, uint32_t& lo) {
    __nv_bfloat16 ha = __float2bfloat16_rn(a);
    __nv_bfloat16 hb = __float2bfloat16_rn(b);
    __nv_bfloat16 la = __float2bfloat16_rn(a - __bfloat162float(ha));
    __nv_bfloat16 lb = __float2bfloat16_rn(b - __bfloat162float(hb));
    hi = (uint32_t)__bfloat16_as_ushort(ha) | ((uint32_t)__bfloat16_as_ushort(hb) << 16);
    lo = (uint32_t)__bfloat16_as_ushort(la) | ((uint32_t)__bfloat16_as_ushort(lb) << 16);
}

__device__ __forceinline__ void mma16816(float c[4], const uint32_t a[4],
                                         uint32_t b0, uint32_t b1) {
    asm volatile(
        "mma.sync.aligned.m16n8k16.row.col.f32.bf16.bf16.f32 "
        "{%0,%1,%2,%3}, {%4,%5,%6,%7}, {%8,%9}, {%0,%1,%2,%3};"
        : "+f"(c[0]), "+f"(c[1]), "+f"(c[2]), "+f"(c[3])
        : "r"(a[0]), "r"(a[1]), "r"(a[2]), "r"(a[3]), "r"(b0), "r"(b1));
}

__device__ __forceinline__ void ldsm_x4(uint32_t r[4], uint32_t addr) {
    asm volatile("ldmatrix.sync.aligned.m8n8.x4.shared.b16 {%0,%1,%2,%3}, [%4];"
        : "=r"(r[0]), "=r"(r[1]), "=r"(r[2]), "=r"(r[3]) : "r"(addr));
}

// ===========================================================================
// d4 = relu(d1 @ w1 + b1)   [64,256]
// ===========================================================================
__global__ void k_d4(const float* __restrict__ d1, const float* __restrict__ w1,
                     const float* __restrict__ b1) {
    __shared__ float row[FEAT];
    int b = blockIdx.x, c = threadIdx.x;
    for (int i = c; i < FEAT; i += blockDim.x) row[i] = d1[b * FEAT + i];
    __syncthreads();
    float acc = b1[c];
#pragma unroll 8
    for (int d = 0; d < FEAT; d++) acc = fmaf(row[d], w1[d * COMP + c], acc);
    g_d4[b * COMP + c] = fmaxf(acc, 0.f);
}

// ===========================================================================
// 64-row fp32 tile GEMM (round-2 proven). 256 threads, 8x8 microtile.
// ===========================================================================
template <int K, int LDA>
__device__ __forceinline__ void gemm_tile64(const float* __restrict__ A,
                                            const float* __restrict__ Bm,
                                            float acc[8][8]) {
    __shared__ float As[16 * 64];
    __shared__ float Bs[16 * 256];
    int tid  = threadIdx.x;
    int am   = tid >> 2;
    int ak   = (tid & 3) << 2;
    int bn   = (tid & 63) << 2;
    int bk   = (tid >> 6) << 2;
    int rowb = (tid >> 5) << 3;
    int cb   = (tid & 31) << 2;

#pragma unroll
    for (int i = 0; i < 8; i++)
#pragma unroll
        for (int j = 0; j < 8; j++) acc[i][j] = 0.f;

    for (int k0 = 0; k0 < K; k0 += 16) {
        float4 av = *(const float4*)(A + am * LDA + k0 + ak);
        As[(ak + 0) * 64 + am] = av.x;
        As[(ak + 1) * 64 + am] = av.y;
        As[(ak + 2) * 64 + am] = av.z;
        As[(ak + 3) * 64 + am] = av.w;
#pragma unroll
        for (int i = 0; i < 4; i++) {
            *(float4*)(Bs + (bk + i) * 256 + bn) =
                *(const float4*)(Bm + (size_t)(k0 + bk + i) * 256 + bn);
        }
        __syncthreads();
#pragma unroll
        for (int kk = 0; kk < 16; kk++) {
            float4 a0 = *(const float4*)(As + kk * 64 + rowb);
            float4 a1 = *(const float4*)(As + kk * 64 + rowb + 4);
            float4 b0 = *(const float4*)(Bs + kk * 256 + cb);
            float4 b1 = *(const float4*)(Bs + kk * 256 + cb + 128);
            float a[8]  = {a0.x, a0.y, a0.z, a0.w, a1.x, a1.y, a1.z, a1.w};
            float bb[8] = {b0.x, b0.y, b0.z, b0.w, b1.x, b1.y, b1.z, b1.w};
#pragma unroll
            for (int i = 0; i < 8; i++)
#pragma unroll
                for (int j = 0; j < 8; j++)
                    acc[i][j] = fmaf(a[i], bb[j], acc[i][j]);
        }
        __syncthreads();
    }
}

// ===========================================================================
// y2[h][b][c] = d4[b,:] @ W_h[256:512,:]   grid NHEAD, block 256.
// ===========================================================================
__global__ void __launch_bounds__(256)
k_y2(const float* __restrict__ W) {
    int h = blockIdx.x;
    float acc[8][8];
    gemm_tile64<COMP, COMP>(g_d4, W + (size_t)h * 512 * 256 + 256 * 256, acc);
    int tid  = threadIdx.x;
    int rowb = (tid >> 5) << 3;
    int cb   = (tid & 31) << 2;
#pragma unroll
    for (int i = 0; i < 8; i++)
#pragma unroll
        for (int j = 0; j < 8; j++) {
            int c = (j < 4) ? cb + j : cb + 124 + j;
            g_y2[((size_t)h * 64 + rowb + i) * 256 + c] = acc[i][j];
        }
}

// ===========================================================================
// Weight split prep (fused): blocks 0..7 -> W^T split (k_att);
// blocks 8..9 -> w1/wv transposed split (k_proj). grid 10, block 256.
// ===========================================================================
__global__ void __launch_bounds__(256)
k_wsplit(const float* __restrict__ W, const float* __restrict__ w1,
         const float* __restrict__ wv) {
    if (blockIdx.x < 8) {
        int h = blockIdx.x;
        for (int i = threadIdx.x; i < 256 * 256; i += 256) {
            int k = i >> 8, c = i & 255;
            float v = W[((size_t)h * 512 + k) * 256 + c];
            __nv_bfloat16 hi = __float2bfloat16_rn(v);
            __nv_bfloat16 lo = __float2bfloat16_rn(v - __bfloat162float(hi));
            size_t o = ((size_t)h * 256 + c) * 256 + k;
            g_Wth[o] = hi;
            g_Wtl[o] = lo;
        }
    } else {
        int path = blockIdx.x - 8;
        const float* w = path ? wv : w1;
        for (int i = threadIdx.x; i < 256 * 512; i += 256) {
            int c = i >> 9, k = i & 511;
            float v = w[(size_t)k * 256 + c];
            __nv_bfloat16 hi = __float2bfloat16_rn(v);
            __nv_bfloat16 lo = __float2bfloat16_rn(v - __bfloat162float(hi));
            size_t o = ((size_t)path * 256 + c) * 512 + k;
            g_wpth[o] = hi;
            g_wptl[o] = lo;
        }
    }
}

// ===========================================================================
// k_proj via HMMA bf16-split + ldmatrix (round-8 proven).
// grid (2 cx, 2 path, 256 mblk), blk 256.
// ===========================================================================
#define PROJ_SMEM_WORDS 18560
#define PROJ_SMEM_BYTES (PROJ_SMEM_WORDS * 4)

__global__ void __launch_bounds__(256, 2)
k_proj_mma(const float* __restrict__ d2, const float* __restrict__ b1) {
    extern __shared__ __align__(16) uint32_t sm[];
    uint32_t* Ah = sm;
    uint32_t* Al = sm + 4608;
    uint32_t* Bh = sm + 9216;
    uint32_t* Bl = sm + 13824;
    float*    b1s = (float*)(sm + 18432);

    const int cx = blockIdx.x, path = blockIdx.y, zb = blockIdx.z;
    const int m0 = zb * 128;
    const int tid = threadIdx.x;
    const int wid = tid >> 5;
    const int lane = tid & 31;
    const int g  = lane >> 2;
    const int tg = lane & 3;
    const int m0w = wid * 16;

    if (path == 0 && tid < 128) b1s[tid] = b1[cx * 128 + tid];

    const uint32_t smb = smem_u32(sm);
    const int arow = m0w + (lane & 7) + ((lane >> 3) & 1) * 8;
    const int akoff = (lane >> 4) * 4;
    const uint32_t aaddr_h = smb + (uint32_t)(arow * 36 + akoff) * 4;
    const uint32_t aaddr_l = aaddr_h + 4608u * 4;
    const int brow = (lane & 7) + ((lane >> 4) << 3);
    const int bkoff = ((lane >> 3) & 1) * 4;
    const uint32_t baddr_h = smb + (uint32_t)(9216 + brow * 36 + bkoff) * 4;
    const uint32_t baddr_l = baddr_h + 4608u * 4;

    float acc[16][4];
#pragma unroll
    for (int n8 = 0; n8 < 16; n8++)
#pragma unroll
        for (int e = 0; e < 4; e++) acc[n8][e] = 0.f;

    const __nv_bfloat16* Wh = g_wpth + ((size_t)path * 256 + cx * 128) * 512;
    const __nv_bfloat16* Wl = g_wptl + ((size_t)path * 256 + cx * 128) * 512;

    for (int ch = 0; ch < 8; ch++) {
        __syncthreads();
        for (int t = tid; t < 2048; t += 256) {
            int r = t >> 4, j = t & 15;
            float4 v = *(const float4*)(d2 + (size_t)(m0 + r) * 512 + ch * 64 + j * 4);
            uint32_t hi0, lo0, hi1, lo1;
            split2(v.x, v.y, hi0, lo0);
            split2(v.z, v.w, hi1, lo1);
            Ah[r * 36 + j * 2]     = hi0;
            Ah[r * 36 + j * 2 + 1] = hi1;
            Al[r * 36 + j * 2]     = lo0;
            Al[r * 36 + j * 2 + 1] = lo1;
        }
        for (int t = tid; t < 2048; t += 256) {
            int n = t >> 4, j = t & 15;
            int plane = j >> 3, j8 = j & 7;
            const uint4* srow = (const uint4*)((plane ? Wl : Wh) + (size_t)n * 512 + ch * 64);
            uint32_t* dstp = (plane ? Bl : Bh) + n * 36 + j8 * 4;
            *(uint4*)dstp = srow[j8];
        }
        __syncthreads();

#pragma unroll
        for (int ks = 0; ks < 4; ks++) {
            const uint32_t kb = (uint32_t)(ks * 8) * 4;
            uint32_t ah[4], al[4];
            ldsm_x4(ah, aaddr_h + kb);
            ldsm_x4(al, aaddr_l + kb);
#pragma unroll
            for (int p = 0; p < 8; p++) {
                uint32_t bh[4], bl[4];
                const uint32_t bo = (uint32_t)(p * 16 * 36) * 4 + kb;
                ldsm_x4(bh, baddr_h + bo);
                ldsm_x4(bl, baddr_l + bo);
                mma16816(acc[2 * p],     ah, bh[0], bh[1]);
                mma16816(acc[2 * p],     ah, bl[0], bl[1]);
                mma16816(acc[2 * p],     al, bh[0], bh[1]);
                mma16816(acc[2 * p + 1], ah, bh[2], bh[3]);
                mma16816(acc[2 * p + 1], ah, bl[2], bl[3]);
                mma16816(acc[2 * p + 1], al, bh[2], bh[3]);
            }
        }
    }

    const int r0 = m0w + g, r1 = r0 + 8;
    const int R0 = m0 + r0, R1 = m0 + r1;
    if (path == 0) {
        uint32_t* dst0 = g_d3p + (size_t)R0 * 256;
        uint32_t* dst1 = g_d3p + (size_t)R1 * 256;
#pragma unroll
        for (int n8 = 0; n8 < 16; n8++) {
            const int cc = n8 * 8 + tg * 2;
            const int word = cx * 64 + n8 * 4 + tg;
            const float bb0 = b1s[cc], bb1 = b1s[cc + 1];
            uint32_t hi, lo;
            float v0 = fmaxf(acc[n8][0] + bb0, 0.f);
            float v1 = fmaxf(acc[n8][1] + bb1, 0.f);
            split2(v0, v1, hi, lo);
            dst0[word] = hi; dst0[128 + word] = lo;
            float v2 = fmaxf(acc[n8][2] + bb0, 0.f);
            float v3 = fmaxf(acc[n8][3] + bb1, 0.f);
            split2(v2, v3, hi, lo);
            dst1[word] = hi; dst1[128 + word] = lo;
        }
    } else {
        const int s0 = R0 >> 6, b0i = R0 & 63;
        const int s1 = R1 >> 6, b1i = R1 & 63;
        float* t0 = g_tv + ((size_t)b0i * 512 + s0) * 256 + cx * 128;
        float* t1 = g_tv + ((size_t)b1i * 512 + s1) * 256 + cx * 128;
#pragma unroll
        for (int n8 = 0; n8 < 16; n8++) {
            const int cc = n8 * 8 + tg * 2;
            *(float2*)(t0 + cc) = make_float2(tanhf(acc[n8][0]), tanhf(acc[n8][1]));
            *(float2*)(t1 + cc) = make_float2(tanhf(acc[n8][2]), tanhf(acc[n8][3]));
        }
    }
}

// ===========================================================================
// k_att via HMMA + cp.async 2-stage pipeline. grid (2 cx, 8 h, 256), blk 256.
// k=32 chunks (8 chunks), double-buffered. Buf layout (words, pitch 20):
//   Ah [0,2560) Al [2560,5120) Bh [5120,7680) Bl [7680,10240); buf1 at 10240.
//   Ps at word 20480. y2 read from global in epilogue.
// ===========================================================================
#define ATT_BUF_WORDS 10240
#define ATT_SMEM_WORDS (2 * ATT_BUF_WORDS + 128)
#define ATT_SMEM_BYTES (ATT_SMEM_WORDS * 4)

__global__ void __launch_bounds__(256, 2)
k_att_mma(const float* __restrict__ P) {
    extern __shared__ __align__(16) uint32_t sm[];
    float* Ps = (float*)(sm + 2 * ATT_BUF_WORDS);

    const int cx = blockIdx.x, h = blockIdx.y, zb = blockIdx.z;
    const int m0 = zb * 128;
    const int tid = threadIdx.x;
    const int wid = tid >> 5;
    const int lane = tid & 31;
    const int g  = lane >> 2;
    const int tg = lane & 3;
    const int m0w = wid * 16;

    if (tid < 128) Ps[tid] = P[h * 256 + cx * 128 + tid];

    const uint32_t smb = smem_u32(sm);
    const int arow = m0w + (lane & 7) + ((lane >> 3) & 1) * 8;
    const int akoff = (lane >> 4) * 4;
    const uint32_t aoff_h = (uint32_t)(arow * 20 + akoff) * 4;
    const uint32_t aoff_l = aoff_h + 2560u * 4;
    const int brow = (lane & 7) + ((lane >> 4) << 3);
    const int bkoff = ((lane >> 3) & 1) * 4;
    const uint32_t boff_h = (uint32_t)(5120 + brow * 20 + bkoff) * 4;
    const uint32_t boff_l = boff_h + 2560u * 4;

    const __nv_bfloat16* Wh = g_Wth + ((size_t)h * 256 + cx * 128) * 256;
    const __nv_bfloat16* Wl = g_Wtl + ((size_t)h * 256 + cx * 128) * 256;

    // per-thread cp.async decomposition (8 ops/thread/chunk)
    const int t_sel = tid >> 7;            // 0: A for t<... -> use full formula below

    float acc[16][4];
#pragma unroll
    for (int n8 = 0; n8 < 16; n8++)
#pragma unroll
        for (int e = 0; e < 4; e++) acc[n8][e] = 0.f;

    // ---- issue helper (inlined twice) ----
    auto issue = [&](int ch, uint32_t dstb) {
#pragma unroll
        for (int t = tid; t < 2048; t += 256) {
            int sel = t >> 10;             // 0 = A, 1 = B
            int q = t & 1023;
            int r = q >> 3;                // row / col
            int j = q & 7;
            int pl = j >> 2;               // 0 hi, 1 lo
            int w4 = (j & 3) * 4;          // word offset within 16-word chunk row
            if (sel == 0) {
                const void* src = g_d3p + (size_t)(m0 + r) * 256 + pl * 128 + ch * 16 + w4;
                uint32_t dst = dstb + (uint32_t)((pl ? 2560 : 0) + r * 20 + w4) * 4;
                CP16(dst, src);
            } else {
                const __nv_bfloat16* bp = pl ? Wl : Wh;
                const void* src = bp + (size_t)r * 256 + ch * 32 + w4 * 2;
                uint32_t dst = dstb + (uint32_t)((pl ? 7680 : 5120) + r * 20 + w4) * 4;
                CP16(dst, src);
            }
        }
        CP_COMMIT();
    };

    issue(0, smb);

    for (int ch = 0; ch < 8; ch++) {
        const uint32_t bufb = smb + (uint32_t)(ch & 1) * (ATT_BUF_WORDS * 4);
        if (ch + 1 < 8) {
            issue(ch + 1, smb + (uint32_t)((ch + 1) & 1) * (ATT_BUF_WORDS * 4));
            CP_WAIT(1);
        } else {
            CP_WAIT(0);
        }
        __syncthreads();

#pragma unroll
        for (int ks = 0; ks < 2; ks++) {
            const uint32_t kb = (uint32_t)(ks * 8) * 4;
            uint32_t ah[4], al[4];
            ldsm_x4(ah, bufb + aoff_h + kb);
            ldsm_x4(al, bufb + aoff_l + kb);
#pragma unroll
            for (int p = 0; p < 8; p++) {
                uint32_t bh[4], bl[4];
                const uint32_t bo = (uint32_t)(p * 16 * 20) * 4 + kb;
                ldsm_x4(bh, bufb + boff_h + bo);
                ldsm_x4(bl, bufb + boff_l + bo);
                mma16816(acc[2 * p],     ah, bh[0], bh[1]);
                mma16816(acc[2 * p],     ah, bl[0], bl[1]);
                mma16816(acc[2 * p],     al, bh[0], bh[1]);
                mma16816(acc[2 * p + 1], ah, bh[2], bh[3]);
                mma16816(acc[2 * p + 1], ah, bl[2], bl[3]);
                mma16816(acc[2 * p + 1], al, bh[2], bh[3]);
            }
        }
        __syncthreads();
    }

    // ---- epilogue: y2 from global (__ldg), P from smem ----
    const int r0 = m0w + g, r1 = r0 + 8;
    const int b0 = (m0 + r0) & 63, b1v = (m0 + r1) & 63;
    const float* y2p = g_y2 + (size_t)h * 64 * 256 + cx * 128;
    float ps0 = 0.f, ps1 = 0.f;
#pragma unroll
    for (int n8 = 0; n8 < 16; n8++) {
        const int cc0 = n8 * 8 + tg * 2;
        const float p0 = Ps[cc0], p1 = Ps[cc0 + 1];
        const float2 y0 = __ldg((const float2*)(y2p + b0 * 256 + cc0));
        const float2 y1 = __ldg((const float2*)(y2p + b1v * 256 + cc0));
        ps0 += tanhf(acc[n8][0] + y0.x) * p0 + tanhf(acc[n8][1] + y0.y) * p1;
        ps1 += tanhf(acc[n8][2] + y1.x) * p0 + tanhf(acc[n8][3] + y1.y) * p1;
    }
    ps0 += __shfl_xor_sync(0xffffffffu, ps0, 1);
    ps0 += __shfl_xor_sync(0xffffffffu, ps0, 2);
    ps1 += __shfl_xor_sync(0xffffffffu, ps1, 1);
    ps1 += __shfl_xor_sync(0xffffffffu, ps1, 2);
    if (tg == 0) {
        float* dst = g_attsp + (size_t)cx * (NHEAD * BATCH * SEQ);
        const int R0 = m0 + r0, R1 = m0 + r1;
        dst[((size_t)h * 64 + (R0 & 63)) * 512 + (R0 >> 6)] = ps0;
        dst[((size_t)h * 64 + (R1 & 63)) * 512 + (R1 >> 6)] = ps1;
    }
}

// ===========================================================================
// Row softmax over S=512, summing the two c-half partials. grid 512, blk 256.
// ===========================================================================
__global__ void k_softmax() {
    __shared__ float red[256];
    int row = blockIdx.x, tid = threadIdx.x;
    const float* a0 = g_attsp + (size_t)row * 512;
    const float* a1 = a0 + (size_t)NHEAD * BATCH * SEQ;
    float v0 = a0[tid] + a1[tid];
    float v1 = a0[tid + 256] + a1[tid + 256];
    red[tid] = fmaxf(v0, v1);
    __syncthreads();
    for (int o = 128; o > 0; o >>= 1) {
        if (tid < o) red[tid] = fmaxf(red[tid], red[tid + o]);
        __syncthreads();
    }
    float m = red[0];
    __syncthreads();
    float e0 = expf(v0 - m), e1 = expf(v1 - m);
    red[tid] = e0 + e1;
    __syncthreads();
    for (int o = 128; o > 0; o >>= 1) {
        if (tid < o) red[tid] += red[tid + o];
        __syncthreads();
    }
    float inv = 1.f / red[0];
    g_scores[(size_t)row * 512 + tid]       = e0 * inv;
    g_scores[(size_t)row * 512 + tid + 256] = e1 * inv;
}

// ===========================================================================
// Partial vs over s-chunks. grid (BATCH, 8), block 256.
// ===========================================================================
__global__ void __launch_bounds__(256)
k_out1() {
    __shared__ float sc[512];
    int b = blockIdx.x, sb = blockIdx.y, tid = threadIdx.x;
    for (int i = tid; i < 512; i += 256) {
        int h = i >> 6, ss = i & 63;
        sc[i] = g_scores[((size_t)h * 64 + b) * 512 + sb * 64 + ss];
    }
    __syncthreads();
    float acc[NHEAD] = {0.f, 0.f, 0.f, 0.f, 0.f, 0.f, 0.f, 0.f};
    const float* tvb = g_tv + ((size_t)b * 512 + sb * 64) * 256 + tid;
#pragma unroll 8
    for (int ss = 0; ss < 64; ss++) {
        float t = tvb[(size_t)ss * 256];
#pragma unroll
        for (int h = 0; h < NHEAD; h++) acc[h] = fmaf(sc[h * 64 + ss], t, acc[h]);
    }
#pragma unroll
    for (int h = 0; h < NHEAD; h++)
        g_vsp[((size_t)sb * 64 + b) * 2048 + h * 256 + tid] = acc[h];
}

// ===========================================================================
// Reduce partials + final cc. grid 64, block 128.
// ===========================================================================
__global__ void __launch_bounds__(128)
k_out2(const float* __restrict__ wcc, const float* __restrict__ bcc,
       float* __restrict__ out) {
    __shared__ float vsf[2048];
    int b = blockIdx.x, tid = threadIdx.x;
    for (int i = tid; i < 2048; i += 128) {
        float v = 0.f;
#pragma unroll
        for (int sb = 0; sb < 8; sb++)
            v += g_vsp[((size_t)sb * 64 + b) * 2048 + i];
        vsf[i] = v;
    }
    __syncthreads();
    float o = bcc[tid];
#pragma unroll 8
    for (int i = 0; i < 2048; i++) o = fmaf(vsf[i], wcc[i * 128 + tid], o);
    out[b * 128 + tid] = fmaxf(o, 0.f);
}

// ===========================================================================
extern "C" void kernel_launch(void* const* d_in, const int* in_sizes, int n_in,
                              void* d_out, int out_size) {
    const float* d1  = (const float*)d_in[0];
    const float* d2  = (const float*)d_in[1];
    const float* w1  = (const float*)d_in[2];
    const float* b1  = (const float*)d_in[3];
    const float* W   = (const float*)d_in[4];
    const float* P   = (const float*)d_in[5];
    const float* wv  = (const float*)d_in[6];
    const float* wcc = (const float*)d_in[7];
    const float* bcc = (const float*)d_in[8];
    float* out = (float*)d_out;

    cudaFuncSetAttribute(k_att_mma, cudaFuncAttributeMaxDynamicSharedMemorySize,
                         ATT_SMEM_BYTES);
    cudaFuncSetAttribute(k_proj_mma, cudaFuncAttributeMaxDynamicSharedMemorySize,
                         PROJ_SMEM_BYTES);

    k_d4<<<BATCH, COMP>>>(d1, w1, b1);
    k_y2<<<NHEAD, 256>>>(W);
    k_wsplit<<<10, 256>>>(W, w1, wv);
    k_proj_mma<<<dim3(2, 2, 256), 256, PROJ_SMEM_BYTES>>>(d2, b1);
    k_att_mma<<<dim3(2, NHEAD, SEQ / 2), 256, ATT_SMEM_BYTES>>>(P);
    k_softmax<<<NHEAD * BATCH, 256>>>();
    k_out1<<<dim3(BATCH, 8), 256>>>();
    k_out2<<<BATCH, 128>>>(wcc, bcc, out);
}